// round 2
// baseline (speedup 1.0000x reference)
#include <cuda_runtime.h>
#include <cuda_bf16.h>
#include <math.h>

#define BB 16
#define NN 4096
#define SS 1024
#define KK 32
#define GG (BB*SS)            // 16384 groups
#define MAXP (GG*KK)          // 524288 worst-case positions
#define TOTAL_DIV 524288.0    // BN divisor: B*K*S

// ---------------- scratch (static device globals; no runtime allocation) ----
__device__ float  g_x0[(size_t)MAXP * 8];     // compacted input features (padded to 8 ch)
__device__ float  g_wt[MAXP];                  // multiplicity weight per position
__device__ int    g_gstart[GG];
__device__ int    g_gcnt[GG];
__device__ int    g_ptot;
__device__ float  g_y1[(size_t)MAXP * 64];
__device__ float  g_y2[(size_t)MAXP * 64];
__device__ float  g_y3[(size_t)MAXP * 128];
__device__ double g_sum[3][128];
__device__ double g_sumsq[3][128];
__device__ float  g_A[3][128];
__device__ float  g_Bc[3][128];

// ---------------- init ------------------------------------------------------
__global__ void init_kernel() {
    int t = blockIdx.x * blockDim.x + threadIdx.x;
    if (t == 0) g_ptot = 0;
    if (t < 384) {
        ((double*)g_sum)[t]   = 0.0;
        ((double*)g_sumsq)[t] = 0.0;
    }
}

// ---------------- farthest point sampling (bit-exact) -----------------------
// one block per batch, 1024 threads, 4 points/thread
__global__ __launch_bounds__(1024, 1)
void fps_kernel(const float* __restrict__ xyz, float* __restrict__ newxyz) {
    int b = blockIdx.x, tid = threadIdx.x;
    const float* bx = xyz + (size_t)b * 3 * NN;

    float px[4], py[4], pz[4], dist[4];
    {
        float4 x4 = ((const float4*)(bx))[tid];
        float4 y4 = ((const float4*)(bx + NN))[tid];
        float4 z4 = ((const float4*)(bx + 2 * NN))[tid];
        px[0]=x4.x; px[1]=x4.y; px[2]=x4.z; px[3]=x4.w;
        py[0]=y4.x; py[1]=y4.y; py[2]=y4.z; py[3]=y4.w;
        pz[0]=z4.x; pz[1]=z4.y; pz[2]=z4.z; pz[3]=z4.w;
    }
#pragma unroll
    for (int j = 0; j < 4; j++) dist[j] = 1e10f;

    __shared__ float pv[2][32];
    __shared__ int   pi[2][32];
    int lane = tid & 31, wid = tid >> 5;
    int farthest = 0;

    for (int it = 0; it < SS; ++it) {
        float cx = __ldg(bx + farthest);
        float cy = __ldg(bx + NN + farthest);
        float cz = __ldg(bx + 2 * NN + farthest);
        if (tid == 0) {
            newxyz[(size_t)b * 3 * SS + it]            = cx;
            newxyz[(size_t)b * 3 * SS + SS + it]       = cy;
            newxyz[(size_t)b * 3 * SS + 2 * SS + it]   = cz;
        }
        float bv = -1.0f; int bi = 0;
#pragma unroll
        for (int j = 0; j < 4; j++) {
            float dx = __fsub_rn(px[j], cx);
            float dy = __fsub_rn(py[j], cy);
            float dz = __fsub_rn(pz[j], cz);
            float d  = __fadd_rn(__fadd_rn(__fmul_rn(dx, dx), __fmul_rn(dy, dy)),
                                 __fmul_rn(dz, dz));
            float nd = fminf(dist[j], d);
            dist[j] = nd;
            if (nd > bv) { bv = nd; bi = tid * 4 + j; }
        }
        // warp argmax (first-index on ties)
#pragma unroll
        for (int o = 16; o > 0; o >>= 1) {
            float ov = __shfl_xor_sync(0xffffffffu, bv, o);
            int   oi = __shfl_xor_sync(0xffffffffu, bi, o);
            if (ov > bv || (ov == bv && oi < bi)) { bv = ov; bi = oi; }
        }
        int buf = it & 1;
        if (lane == 0) { pv[buf][wid] = bv; pi[buf][wid] = bi; }
        __syncthreads();
        bv = pv[buf][lane]; bi = pi[buf][lane];
#pragma unroll
        for (int o = 16; o > 0; o >>= 1) {
            float ov = __shfl_xor_sync(0xffffffffu, bv, o);
            int   oi = __shfl_xor_sync(0xffffffffu, bi, o);
            if (ov > bv || (ov == bv && oi < bi)) { bv = ov; bi = oi; }
        }
        farthest = bi;
    }
}

// ---------------- ball query + compaction + gather --------------------------
// one warp per group (b, s)
// Distance must match the reference's fp32 arithmetic op-for-op:
//   t  = fma-chain dot (GEMM-style, c order 0,1,2)
//   ns = ((cx*cx + cy*cy) + cz*cz)   plain mul/add (elementwise fusion, no FMA)
//   d  = ((-2*t) + ns) + nd          plain mul/add, this association order
__global__ __launch_bounds__(128)
void query_gather_kernel(const float* __restrict__ xyz,
                         const float* __restrict__ pts,
                         const float* __restrict__ newxyz) {
    int gwarp = (blockIdx.x * blockDim.x + threadIdx.x) >> 5;
    int lane  = threadIdx.x & 31;
    int wslot = (threadIdx.x >> 5) & 3;
    int b = gwarp >> 10, s = gwarp & (SS - 1);

    __shared__ int sgidx[4][KK];
    int* gidx = sgidx[wslot];

    const float* bx = xyz + (size_t)b * 3 * NN;
    float cx = newxyz[(size_t)b * 3 * SS + s];
    float cy = newxyz[(size_t)b * 3 * SS + SS + s];
    float cz = newxyz[(size_t)b * 3 * SS + 2 * SS + s];
    float ns = __fadd_rn(__fadd_rn(__fmul_rn(cx, cx), __fmul_rn(cy, cy)),
                         __fmul_rn(cz, cz));

    int cnt = 0;
    for (int j = 0; j < NN / 32; j++) {
        int i = j * 32 + lane;
        float dx = bx[i], dy = bx[NN + i], dz = bx[2 * NN + i];
        float nd = __fadd_rn(__fadd_rn(__fmul_rn(dx, dx), __fmul_rn(dy, dy)),
                             __fmul_rn(dz, dz));
        float t  = __fmaf_rn(cz, dz, __fmaf_rn(cy, dy, __fmul_rn(cx, dx)));
        float d  = __fadd_rn(__fadd_rn(__fmul_rn(-2.0f, t), ns), nd);
        bool ok = !(d > 0.04f);
        unsigned m = __ballot_sync(0xffffffffu, ok);
        int pos = cnt + __popc(m & ((1u << lane) - 1u));
        if (ok && pos < KK) gidx[pos] = i;
        cnt += __popc(m);
        if (cnt >= KK) break;
    }
    int mcnt = min(cnt, KK);
    __syncwarp();

    int base = 0;
    if (lane == 0) {
        base = atomicAdd(&g_ptot, mcnt);
        g_gstart[gwarp] = base;
        g_gcnt[gwarp]   = mcnt;
    }
    base = __shfl_sync(0xffffffffu, base, 0);

    if (lane < mcnt) {
        int i = gidx[lane];
        const float* bp = pts + (size_t)b * 3 * NN;
        float* dst = g_x0 + (size_t)(base + lane) * 8;
        dst[0] = __fsub_rn(bx[i], cx);
        dst[1] = __fsub_rn(bx[NN + i], cy);
        dst[2] = __fsub_rn(bx[2 * NN + i], cz);
        dst[3] = bp[i];
        dst[4] = bp[NN + i];
        dst[5] = bp[2 * NN + i];
        dst[6] = 0.0f;
        dst[7] = 0.0f;
        g_wt[base + lane] = (lane == 0) ? (float)(KK - mcnt + 1) : 1.0f;
    }
}

// ---------------- layer 1: 8(6)->64, raw conv output ------------------------
__global__ __launch_bounds__(128)
void gemm1_kernel(const float* __restrict__ w0) {
    __shared__ float ws[8][64];
    int tid = threadIdx.x;
    for (int idx = tid; idx < 512; idx += 128) {
        int c = idx >> 6, o = idx & 63;
        ws[c][o] = (c < 6) ? w0[o * 6 + c] : 0.0f;
    }
    __syncthreads();
    int ptot = g_ptot;
    for (int p = blockIdx.x * 128 + tid; p < ptot; p += gridDim.x * 128) {
        const float4* xr = (const float4*)(g_x0 + (size_t)p * 8);
        float4 a = xr[0], b4 = xr[1];
        float x[6] = { a.x, a.y, a.z, a.w, b4.x, b4.y };
        float acc[64];
#pragma unroll
        for (int o = 0; o < 64; o++) acc[o] = 0.0f;
#pragma unroll
        for (int c = 0; c < 6; c++)
#pragma unroll
            for (int o = 0; o < 64; o++) acc[o] = fmaf(x[c], ws[c][o], acc[o]);
        float4* out = (float4*)(g_y1 + (size_t)p * 64);
#pragma unroll
        for (int o = 0; o < 16; o++)
            out[o] = make_float4(acc[4*o], acc[4*o+1], acc[4*o+2], acc[4*o+3]);
    }
}

// ---------------- layers 2/3: fused BN+ReLU on input, 64->COUT --------------
// LAYER_IN: which stats normalize the input. COUT=64 -> writes g_y2, COUT=128 -> g_y3
template<int COUT, int LAYER_IN>
__global__ __launch_bounds__(128)
void gemm_bn_kernel(const float* __restrict__ W) {
    constexpr int TX = COUT / 8;     // 8 or 16
    constexpr int TY = 128 / TX;     // 16 or 8
    constexpr int PT = 64 / TY;      // 4 or 8 positions per thread

    __shared__ float Xs[64 * 64];        // [pos][c]
    __shared__ float Ws[64 * COUT];      // [c][o]

    const float* Yin  = (LAYER_IN == 0) ? g_y1 : g_y2;
    float*       Yout = (COUT == 64) ? g_y2 : g_y3;
    const float* A  = g_A[LAYER_IN];
    const float* Bc = g_Bc[LAYER_IN];

    int tid = threadIdx.x;
    int tx = tid % TX, ty = tid / TX;

    for (int idx = tid; idx < 64 * COUT; idx += 128) {
        int c = idx & 63, o = idx >> 6;
        Ws[c * COUT + o] = W[o * 64 + c];   // W is (COUT, 64)
    }
    __syncthreads();

    int ptot = g_ptot;
    int ntiles = (ptot + 63) >> 6;
    for (int t = blockIdx.x; t < ntiles; t += gridDim.x) {
        int p0 = t * 64;
        for (int idx = tid; idx < 64 * 64; idx += 128) {
            int c = idx & 63, pl = idx >> 6;
            int p = p0 + pl;
            float v = 0.0f;
            if (p < ptot) {
                float y = Yin[(size_t)p * 64 + c];
                v = fmaxf(fmaf(A[c], y, Bc[c]), 0.0f);
            }
            Xs[pl * 64 + c] = v;
        }
        __syncthreads();

        float acc[PT][8];
#pragma unroll
        for (int j = 0; j < PT; j++)
#pragma unroll
            for (int i = 0; i < 8; i++) acc[j][i] = 0.0f;

#pragma unroll
        for (int c = 0; c < 64; c++) {
            float wv[8], xv[PT];
#pragma unroll
            for (int i = 0; i < 8; i++) wv[i] = Ws[c * COUT + tx + i * TX];
#pragma unroll
            for (int j = 0; j < PT; j++) xv[j] = Xs[(ty * PT + j) * 64 + c];
#pragma unroll
            for (int j = 0; j < PT; j++)
#pragma unroll
                for (int i = 0; i < 8; i++)
                    acc[j][i] = fmaf(xv[j], wv[i], acc[j][i]);
        }

#pragma unroll
        for (int j = 0; j < PT; j++) {
            int p = p0 + ty * PT + j;
            if (p < ptot) {
#pragma unroll
                for (int i = 0; i < 8; i++)
                    Yout[(size_t)p * COUT + tx + i * TX] = acc[j][i];
            }
        }
        __syncthreads();
    }
}

// ---------------- weighted per-channel stats --------------------------------
template<int COUT, int LAYER>
__global__ void stats_kernel() {
    const float* Y = (LAYER == 0) ? g_y1 : (LAYER == 1 ? g_y2 : g_y3);
    int o = threadIdx.x;               // COUT threads
    int ptot = g_ptot;
    double s = 0.0, sq = 0.0;
    int ntiles = (ptot + 255) >> 8;
    for (int t = blockIdx.x; t < ntiles; t += gridDim.x) {
        int pend = min(ptot, t * 256 + 256);
        for (int p = t * 256; p < pend; ++p) {
            float w = g_wt[p];
            float v = Y[(size_t)p * COUT + o];
            float wv = w * v;
            s  += (double)wv;
            sq += (double)(wv * v);
        }
    }
    atomicAdd(&g_sum[LAYER][o], s);
    atomicAdd(&g_sumsq[LAYER][o], sq);
}

// ---------------- finalize BN affine ----------------------------------------
__global__ void finalize_kernel(const float* __restrict__ gamma,
                                const float* __restrict__ beta,
                                int layer, int cout) {
    int o = threadIdx.x;
    if (o >= cout) return;
    double mean = g_sum[layer][o] / TOTAL_DIV;
    double var  = g_sumsq[layer][o] / TOTAL_DIV - mean * mean;
    double inv  = 1.0 / sqrt(var + 1e-5);
    double ga   = (double)gamma[o];
    g_A[layer][o]  = (float)(ga * inv);
    g_Bc[layer][o] = (float)((double)beta[o] - mean * ga * inv);
}

// ---------------- final BN+ReLU + max over group ----------------------------
__global__ __launch_bounds__(128)
void maxpool_kernel(float* __restrict__ feats) {
    int g = blockIdx.x;
    int o = threadIdx.x;               // 128
    int m  = g_gcnt[g];
    int st = g_gstart[g];
    float Aa = g_A[2][o], Bb = g_Bc[2][o];
    float mx = -3.4e38f;
    for (int k = 0; k < m; k++) {
        float y = g_y3[(size_t)(st + k) * 128 + o];
        float z = fmaxf(fmaf(Aa, y, Bb), 0.0f);
        mx = fmaxf(mx, z);
    }
    int b = g >> 10, s = g & (SS - 1);
    feats[((size_t)b * 128 + o) * SS + s] = mx;
}

// ---------------- launch ----------------------------------------------------
extern "C" void kernel_launch(void* const* d_in, const int* in_sizes, int n_in,
                              void* d_out, int out_size) {
    const float* xyz = (const float*)d_in[0];
    const float* pts = (const float*)d_in[1];
    const float* w0  = (const float*)d_in[2];
    const float* g0  = (const float*)d_in[4];
    const float* be0 = (const float*)d_in[5];
    const float* w1  = (const float*)d_in[6];
    const float* g1  = (const float*)d_in[8];
    const float* be1 = (const float*)d_in[9];
    const float* w2  = (const float*)d_in[10];
    const float* g2  = (const float*)d_in[12];
    const float* be2 = (const float*)d_in[13];

    float* out    = (float*)d_out;
    float* newxyz = out;                              // (B,3,S)
    float* feats  = out + (size_t)BB * 3 * SS;        // (B,128,S)

    init_kernel<<<2, 256>>>();
    fps_kernel<<<BB, 1024>>>(xyz, newxyz);
    query_gather_kernel<<<GG / 4, 128>>>(xyz, pts, newxyz);

    gemm1_kernel<<<1024, 128>>>(w0);
    stats_kernel<64, 0><<<1024, 64>>>();
    finalize_kernel<<<1, 128>>>(g0, be0, 0, 64);

    gemm_bn_kernel<64, 0><<<2048, 128>>>(w1);
    stats_kernel<64, 1><<<1024, 64>>>();
    finalize_kernel<<<1, 128>>>(g1, be1, 1, 64);

    gemm_bn_kernel<128, 1><<<2048, 128>>>(w2);
    stats_kernel<128, 2><<<1024, 128>>>();
    finalize_kernel<<<1, 128>>>(g2, be2, 2, 128);

    maxpool_kernel<<<GG, 128>>>(feats);
}

// round 3
// speedup vs baseline: 2.2417x; 2.2417x over previous
#include <cuda_runtime.h>
#include <cuda_bf16.h>
#include <math.h>

#define BB 16
#define NN 4096
#define SS 1024
#define KK 32
#define GG (BB*SS)            // 16384 groups
#define MAXP (GG*KK)          // 524288 worst-case positions
#define TOTAL_DIV 524288.0    // BN divisor: B*K*S

// ---------------- scratch (static device globals; no runtime allocation) ----
__device__ float  g_x0[(size_t)MAXP * 8];     // compacted input features (padded to 8 ch)
__device__ float  g_wt[MAXP];                  // multiplicity weight per position
__device__ int    g_gstart[GG];
__device__ int    g_gcnt[GG];
__device__ int    g_ptot;
__device__ float  g_y1[(size_t)MAXP * 64];
__device__ float  g_y2[(size_t)MAXP * 64];
__device__ float  g_y3[(size_t)MAXP * 128];
__device__ double g_sum[3][128];
__device__ double g_sumsq[3][128];
__device__ float  g_A[3][128];
__device__ float  g_Bc[3][128];

// ---------------- init ------------------------------------------------------
__global__ void init_kernel() {
    int t = blockIdx.x * blockDim.x + threadIdx.x;
    if (t == 0) g_ptot = 0;
    if (t < 384) {
        ((double*)g_sum)[t]   = 0.0;
        ((double*)g_sumsq)[t] = 0.0;
    }
}

// ---------------- farthest point sampling (bit-exact, latency-optimized) ----
// one block per batch, 512 threads, 8 points/thread.
// Per iteration: local argmax in regs -> REDUX.SYNC warp max on float bits ->
// ballot lowest-lane index recovery -> leaders to double-buffered smem ->
// ONE barrier -> every thread scans 16 warp entries (first-index tiebreak).
__global__ __launch_bounds__(512, 1)
void fps_kernel(const float* __restrict__ xyz, float* __restrict__ newxyz) {
    int b = blockIdx.x, tid = threadIdx.x;
    const float* bx = xyz + (size_t)b * 3 * NN;

    float px[8], py[8], pz[8], dist[8];
    {
        const float4* x4 = (const float4*)(bx);
        const float4* y4 = (const float4*)(bx + NN);
        const float4* z4 = (const float4*)(bx + 2 * NN);
#pragma unroll
        for (int h = 0; h < 2; h++) {
            float4 xa = x4[tid * 2 + h], ya = y4[tid * 2 + h], za = z4[tid * 2 + h];
            px[4*h+0]=xa.x; px[4*h+1]=xa.y; px[4*h+2]=xa.z; px[4*h+3]=xa.w;
            py[4*h+0]=ya.x; py[4*h+1]=ya.y; py[4*h+2]=ya.z; py[4*h+3]=ya.w;
            pz[4*h+0]=za.x; pz[4*h+1]=za.y; pz[4*h+2]=za.z; pz[4*h+3]=za.w;
        }
    }
#pragma unroll
    for (int j = 0; j < 8; j++) dist[j] = 1e10f;

    __shared__ unsigned sbits[2][16];
    __shared__ int      sidx[2][16];
    int lane = tid & 31, wid = tid >> 5;
    int farthest = 0;

    for (int it = 0; it < SS; ++it) {
        float cx = __ldg(bx + farthest);
        float cy = __ldg(bx + NN + farthest);
        float cz = __ldg(bx + 2 * NN + farthest);
        if (tid == 0) {
            newxyz[(size_t)b * 3 * SS + it]          = cx;
            newxyz[(size_t)b * 3 * SS + SS + it]     = cy;
            newxyz[(size_t)b * 3 * SS + 2 * SS + it] = cz;
        }
        // update dists (bit-exact arithmetic: sub, mul, (x+y)+z)
#pragma unroll
        for (int j = 0; j < 8; j++) {
            float dx = __fsub_rn(px[j], cx);
            float dy = __fsub_rn(py[j], cy);
            float dz = __fsub_rn(pz[j], cz);
            float d  = __fadd_rn(__fadd_rn(__fmul_rn(dx, dx), __fmul_rn(dy, dy)),
                                 __fmul_rn(dz, dz));
            dist[j] = fminf(dist[j], d);
        }
        // local argmax, first-index ties (ascending j, strict >)
        float bv = dist[0]; int bj = 0;
#pragma unroll
        for (int j = 1; j < 8; j++) if (dist[j] > bv) { bv = dist[j]; bj = j; }
        int bi = tid * 8 + bj;

        // warp argmax via REDUX on float bits (dists >= 0 -> u32 monotone)
        unsigned bits = __float_as_uint(bv);
        unsigned wmax = __reduce_max_sync(0xffffffffu, bits);
        unsigned mm   = __ballot_sync(0xffffffffu, bits == wmax);
        int src  = __ffs(mm) - 1;                 // lowest lane = lowest index
        int widx = __shfl_sync(0xffffffffu, bi, src);

        int buf = it & 1;
        if (lane == 0) { sbits[buf][wid] = wmax; sidx[buf][wid] = widx; }
        __syncthreads();

        // every thread scans the 16 warp winners (ascending wid, strict >)
        unsigned fb = sbits[buf][0]; int fi = sidx[buf][0];
#pragma unroll
        for (int w = 1; w < 16; w++) {
            unsigned vb = sbits[buf][w];
            if (vb > fb) { fb = vb; fi = sidx[buf][w]; }
        }
        farthest = fi;
    }
}

// ---------------- ball query + compaction + gather --------------------------
// one warp per group (b, s)
// Distance matches the reference's fp32 arithmetic op-for-op:
//   t  = fma-chain dot (GEMM-style, c order 0,1,2)
//   ns = ((cx*cx + cy*cy) + cz*cz)   plain mul/add (elementwise fusion, no FMA)
//   d  = ((-2*t) + ns) + nd          plain mul/add, this association order
__global__ __launch_bounds__(128)
void query_gather_kernel(const float* __restrict__ xyz,
                         const float* __restrict__ pts,
                         const float* __restrict__ newxyz) {
    int gwarp = (blockIdx.x * blockDim.x + threadIdx.x) >> 5;
    int lane  = threadIdx.x & 31;
    int wslot = (threadIdx.x >> 5) & 3;
    int b = gwarp >> 10, s = gwarp & (SS - 1);

    __shared__ int sgidx[4][KK];
    int* gidx = sgidx[wslot];

    const float* bx = xyz + (size_t)b * 3 * NN;
    float cx = newxyz[(size_t)b * 3 * SS + s];
    float cy = newxyz[(size_t)b * 3 * SS + SS + s];
    float cz = newxyz[(size_t)b * 3 * SS + 2 * SS + s];
    float ns = __fadd_rn(__fadd_rn(__fmul_rn(cx, cx), __fmul_rn(cy, cy)),
                         __fmul_rn(cz, cz));

    int cnt = 0;
    for (int j = 0; j < NN / 32; j++) {
        int i = j * 32 + lane;
        float dx = bx[i], dy = bx[NN + i], dz = bx[2 * NN + i];
        float nd = __fadd_rn(__fadd_rn(__fmul_rn(dx, dx), __fmul_rn(dy, dy)),
                             __fmul_rn(dz, dz));
        float t  = __fmaf_rn(cz, dz, __fmaf_rn(cy, dy, __fmul_rn(cx, dx)));
        float d  = __fadd_rn(__fadd_rn(__fmul_rn(-2.0f, t), ns), nd);
        bool ok = !(d > 0.04f);
        unsigned m = __ballot_sync(0xffffffffu, ok);
        int pos = cnt + __popc(m & ((1u << lane) - 1u));
        if (ok && pos < KK) gidx[pos] = i;
        cnt += __popc(m);
        if (cnt >= KK) break;
    }
    int mcnt = min(cnt, KK);
    __syncwarp();

    int base = 0;
    if (lane == 0) {
        base = atomicAdd(&g_ptot, mcnt);
        g_gstart[gwarp] = base;
        g_gcnt[gwarp]   = mcnt;
    }
    base = __shfl_sync(0xffffffffu, base, 0);

    if (lane < mcnt) {
        int i = gidx[lane];
        const float* bp = pts + (size_t)b * 3 * NN;
        float* dst = g_x0 + (size_t)(base + lane) * 8;
        dst[0] = __fsub_rn(bx[i], cx);
        dst[1] = __fsub_rn(bx[NN + i], cy);
        dst[2] = __fsub_rn(bx[2 * NN + i], cz);
        dst[3] = bp[i];
        dst[4] = bp[NN + i];
        dst[5] = bp[2 * NN + i];
        dst[6] = 0.0f;
        dst[7] = 0.0f;
        g_wt[base + lane] = (lane == 0) ? (float)(KK - mcnt + 1) : 1.0f;
    }
}

// ---------------- layer 1: 8(6)->64, raw conv output ------------------------
__global__ __launch_bounds__(128)
void gemm1_kernel(const float* __restrict__ w0) {
    __shared__ float ws[8][64];
    int tid = threadIdx.x;
    for (int idx = tid; idx < 512; idx += 128) {
        int c = idx >> 6, o = idx & 63;
        ws[c][o] = (c < 6) ? w0[o * 6 + c] : 0.0f;
    }
    __syncthreads();
    int ptot = g_ptot;
    for (int p = blockIdx.x * 128 + tid; p < ptot; p += gridDim.x * 128) {
        const float4* xr = (const float4*)(g_x0 + (size_t)p * 8);
        float4 a = xr[0], b4 = xr[1];
        float x[6] = { a.x, a.y, a.z, a.w, b4.x, b4.y };
        float acc[64];
#pragma unroll
        for (int o = 0; o < 64; o++) acc[o] = 0.0f;
#pragma unroll
        for (int c = 0; c < 6; c++)
#pragma unroll
            for (int o = 0; o < 64; o++) acc[o] = fmaf(x[c], ws[c][o], acc[o]);
        float4* out = (float4*)(g_y1 + (size_t)p * 64);
#pragma unroll
        for (int o = 0; o < 16; o++)
            out[o] = make_float4(acc[4*o], acc[4*o+1], acc[4*o+2], acc[4*o+3]);
    }
}

// ---------------- layers 2/3: fused BN+ReLU on input, 64->COUT --------------
template<int COUT, int LAYER_IN>
__global__ __launch_bounds__(128)
void gemm_bn_kernel(const float* __restrict__ W) {
    constexpr int TX = COUT / 8;     // 8 or 16
    constexpr int TY = 128 / TX;     // 16 or 8
    constexpr int PT = 64 / TY;      // 4 or 8 positions per thread

    __shared__ float Xs[64 * 64];        // [pos][c]
    __shared__ float Ws[64 * COUT];      // [c][o]

    const float* Yin  = (LAYER_IN == 0) ? g_y1 : g_y2;
    float*       Yout = (COUT == 64) ? g_y2 : g_y3;
    const float* A  = g_A[LAYER_IN];
    const float* Bc = g_Bc[LAYER_IN];

    int tid = threadIdx.x;
    int tx = tid % TX, ty = tid / TX;

    for (int idx = tid; idx < 64 * COUT; idx += 128) {
        int c = idx & 63, o = idx >> 6;
        Ws[c * COUT + o] = W[o * 64 + c];   // W is (COUT, 64)
    }
    __syncthreads();

    int ptot = g_ptot;
    int ntiles = (ptot + 63) >> 6;
    for (int t = blockIdx.x; t < ntiles; t += gridDim.x) {
        int p0 = t * 64;
        for (int idx = tid; idx < 64 * 64; idx += 128) {
            int c = idx & 63, pl = idx >> 6;
            int p = p0 + pl;
            float v = 0.0f;
            if (p < ptot) {
                float y = Yin[(size_t)p * 64 + c];
                v = fmaxf(fmaf(A[c], y, Bc[c]), 0.0f);
            }
            Xs[pl * 64 + c] = v;
        }
        __syncthreads();

        float acc[PT][8];
#pragma unroll
        for (int j = 0; j < PT; j++)
#pragma unroll
            for (int i = 0; i < 8; i++) acc[j][i] = 0.0f;

#pragma unroll
        for (int c = 0; c < 64; c++) {
            float wv[8], xv[PT];
#pragma unroll
            for (int i = 0; i < 8; i++) wv[i] = Ws[c * COUT + tx + i * TX];
#pragma unroll
            for (int j = 0; j < PT; j++) xv[j] = Xs[(ty * PT + j) * 64 + c];
#pragma unroll
            for (int j = 0; j < PT; j++)
#pragma unroll
                for (int i = 0; i < 8; i++)
                    acc[j][i] = fmaf(xv[j], wv[i], acc[j][i]);
        }

#pragma unroll
        for (int j = 0; j < PT; j++) {
            int p = p0 + ty * PT + j;
            if (p < ptot) {
#pragma unroll
                for (int i = 0; i < 8; i++)
                    Yout[(size_t)p * COUT + tx + i * TX] = acc[j][i];
            }
        }
        __syncthreads();
    }
}

// ---------------- weighted per-channel stats --------------------------------
template<int COUT, int LAYER>
__global__ void stats_kernel() {
    const float* Y = (LAYER == 0) ? g_y1 : (LAYER == 1 ? g_y2 : g_y3);
    int o = threadIdx.x;               // COUT threads
    int ptot = g_ptot;
    double s = 0.0, sq = 0.0;
    int ntiles = (ptot + 255) >> 8;
    for (int t = blockIdx.x; t < ntiles; t += gridDim.x) {
        int pend = min(ptot, t * 256 + 256);
        for (int p = t * 256; p < pend; ++p) {
            float w = g_wt[p];
            float v = Y[(size_t)p * COUT + o];
            float wv = w * v;
            s  += (double)wv;
            sq += (double)(wv * v);
        }
    }
    atomicAdd(&g_sum[LAYER][o], s);
    atomicAdd(&g_sumsq[LAYER][o], sq);
}

// ---------------- finalize BN affine ----------------------------------------
__global__ void finalize_kernel(const float* __restrict__ gamma,
                                const float* __restrict__ beta,
                                int layer, int cout) {
    int o = threadIdx.x;
    if (o >= cout) return;
    double mean = g_sum[layer][o] / TOTAL_DIV;
    double var  = g_sumsq[layer][o] / TOTAL_DIV - mean * mean;
    double inv  = 1.0 / sqrt(var + 1e-5);
    double ga   = (double)gamma[o];
    g_A[layer][o]  = (float)(ga * inv);
    g_Bc[layer][o] = (float)((double)beta[o] - mean * ga * inv);
}

// ---------------- final BN+ReLU + max over group ----------------------------
__global__ __launch_bounds__(128)
void maxpool_kernel(float* __restrict__ feats) {
    int g = blockIdx.x;
    int o = threadIdx.x;               // 128
    int m  = g_gcnt[g];
    int st = g_gstart[g];
    float Aa = g_A[2][o], Bb = g_Bc[2][o];
    float mx = -3.4e38f;
    for (int k = 0; k < m; k++) {
        float y = g_y3[(size_t)(st + k) * 128 + o];
        float z = fmaxf(fmaf(Aa, y, Bb), 0.0f);
        mx = fmaxf(mx, z);
    }
    int b = g >> 10, s = g & (SS - 1);
    feats[((size_t)b * 128 + o) * SS + s] = mx;
}

// ---------------- launch ----------------------------------------------------
extern "C" void kernel_launch(void* const* d_in, const int* in_sizes, int n_in,
                              void* d_out, int out_size) {
    const float* xyz = (const float*)d_in[0];
    const float* pts = (const float*)d_in[1];
    const float* w0  = (const float*)d_in[2];
    const float* g0  = (const float*)d_in[4];
    const float* be0 = (const float*)d_in[5];
    const float* w1  = (const float*)d_in[6];
    const float* g1  = (const float*)d_in[8];
    const float* be1 = (const float*)d_in[9];
    const float* w2  = (const float*)d_in[10];
    const float* g2  = (const float*)d_in[12];
    const float* be2 = (const float*)d_in[13];

    float* out    = (float*)d_out;
    float* newxyz = out;                              // (B,3,S)
    float* feats  = out + (size_t)BB * 3 * SS;        // (B,128,S)

    init_kernel<<<2, 256>>>();
    fps_kernel<<<BB, 512>>>(xyz, newxyz);
    query_gather_kernel<<<GG / 4, 128>>>(xyz, pts, newxyz);

    gemm1_kernel<<<1024, 128>>>(w0);
    stats_kernel<64, 0><<<1024, 64>>>();
    finalize_kernel<<<1, 128>>>(g0, be0, 0, 64);

    gemm_bn_kernel<64, 0><<<2048, 128>>>(w1);
    stats_kernel<64, 1><<<1024, 64>>>();
    finalize_kernel<<<1, 128>>>(g1, be1, 1, 64);

    gemm_bn_kernel<128, 1><<<2048, 128>>>(w2);
    stats_kernel<128, 2><<<1024, 128>>>();
    finalize_kernel<<<1, 128>>>(g2, be2, 2, 128);

    maxpool_kernel<<<GG, 128>>>(feats);
}

// round 4
// speedup vs baseline: 2.3397x; 1.0437x over previous
#include <cuda_runtime.h>
#include <cuda_bf16.h>
#include <math.h>

#define BB 16
#define NN 4096
#define SS 1024
#define KK 32
#define GG (BB*SS)            // 16384 groups
#define MAXP (GG*KK)          // 524288 worst-case positions
#define TOTAL_DIV 524288.0    // BN divisor: B*K*S

// ---------------- scratch (static device globals; no runtime allocation) ----
__device__ float  g_x0[(size_t)MAXP * 8];     // compacted input features (padded to 8 ch)
__device__ float  g_wt[MAXP];                  // multiplicity weight per position
__device__ int    g_gstart[GG];
__device__ int    g_gcnt[GG];
__device__ int    g_ptot;
__device__ float  g_y1[(size_t)MAXP * 64];
__device__ float  g_y2[(size_t)MAXP * 64];
__device__ float  g_y3[(size_t)MAXP * 128];
__device__ double g_sum[3][128];
__device__ double g_sumsq[3][128];
__device__ float  g_A[3][128];
__device__ float  g_Bc[3][128];

// ---------------- packed f32x2 helpers (per-lane .rn semantics == scalar) ---
__device__ __forceinline__ unsigned long long f2_pack(float lo, float hi) {
    unsigned long long r;
    asm("mov.b64 %0, {%1, %2};" : "=l"(r) : "f"(lo), "f"(hi));
    return r;
}
__device__ __forceinline__ void f2_unpack(unsigned long long v, float& lo, float& hi) {
    asm("mov.b64 {%0, %1}, %2;" : "=f"(lo), "=f"(hi) : "l"(v));
}
__device__ __forceinline__ unsigned long long f2_add(unsigned long long a, unsigned long long b) {
    unsigned long long r;
    asm("add.rn.f32x2 %0, %1, %2;" : "=l"(r) : "l"(a), "l"(b));
    return r;
}
__device__ __forceinline__ unsigned long long f2_mul(unsigned long long a, unsigned long long b) {
    unsigned long long r;
    asm("mul.rn.f32x2 %0, %1, %2;" : "=l"(r) : "l"(a), "l"(b));
    return r;
}

// ---------------- init ------------------------------------------------------
__global__ void init_kernel() {
    int t = blockIdx.x * blockDim.x + threadIdx.x;
    if (t == 0) g_ptot = 0;
    if (t < 384) {
        ((double*)g_sum)[t]   = 0.0;
        ((double*)g_sumsq)[t] = 0.0;
    }
}

// ---------------- farthest point sampling (bit-exact, f32x2 packed) ---------
// one block per batch, 512 threads, 8 points/thread held as 4 f32x2 pairs.
// Update: add.rn.f32x2(p, -c) == __fsub_rn per lane; mul.rn/add.rn likewise,
// so distance values are bit-identical to the scalar version.
__global__ __launch_bounds__(512, 1)
void fps_kernel(const float* __restrict__ xyz, float* __restrict__ newxyz) {
    int b = blockIdx.x, tid = threadIdx.x;
    const float* bx = xyz + (size_t)b * 3 * NN;

    unsigned long long px2[4], py2[4], pz2[4];
    float dist[8];
    {
        const float4* x4 = (const float4*)(bx);
        const float4* y4 = (const float4*)(bx + NN);
        const float4* z4 = (const float4*)(bx + 2 * NN);
#pragma unroll
        for (int h = 0; h < 2; h++) {
            float4 xa = x4[tid * 2 + h], ya = y4[tid * 2 + h], za = z4[tid * 2 + h];
            px2[2*h]   = f2_pack(xa.x, xa.y);
            px2[2*h+1] = f2_pack(xa.z, xa.w);
            py2[2*h]   = f2_pack(ya.x, ya.y);
            py2[2*h+1] = f2_pack(ya.z, ya.w);
            pz2[2*h]   = f2_pack(za.x, za.y);
            pz2[2*h+1] = f2_pack(za.z, za.w);
        }
    }
#pragma unroll
    for (int j = 0; j < 8; j++) dist[j] = 1e10f;

    __shared__ unsigned sbits[2][16];
    __shared__ int      sidx[2][16];
    int lane = tid & 31, wid = tid >> 5;
    int farthest = 0;

    for (int it = 0; it < SS; ++it) {
        float cx = __ldg(bx + farthest);
        float cy = __ldg(bx + NN + farthest);
        float cz = __ldg(bx + 2 * NN + farthest);
        if (tid == 0) {
            newxyz[(size_t)b * 3 * SS + it]          = cx;
            newxyz[(size_t)b * 3 * SS + SS + it]     = cy;
            newxyz[(size_t)b * 3 * SS + 2 * SS + it] = cz;
        }
        unsigned long long ncx = f2_pack(-cx, -cx);
        unsigned long long ncy = f2_pack(-cy, -cy);
        unsigned long long ncz = f2_pack(-cz, -cz);

        // packed distance update: per lane rn(sub), rn(mul), rn((xx+yy)+zz)
#pragma unroll
        for (int k = 0; k < 4; k++) {
            unsigned long long dx = f2_add(px2[k], ncx);
            unsigned long long dy = f2_add(py2[k], ncy);
            unsigned long long dz = f2_add(pz2[k], ncz);
            unsigned long long s  = f2_add(f2_add(f2_mul(dx, dx), f2_mul(dy, dy)),
                                           f2_mul(dz, dz));
            float d0, d1;
            f2_unpack(s, d0, d1);
            dist[2*k]   = fminf(dist[2*k],   d0);
            dist[2*k+1] = fminf(dist[2*k+1], d1);
        }

        // local argmax tree over 8, first-index ties (b>a keeps lower index)
        float v[4]; int ix[4];
#pragma unroll
        for (int k = 0; k < 4; k++) {
            bool g = dist[2*k+1] > dist[2*k];
            v[k]  = g ? dist[2*k+1] : dist[2*k];
            ix[k] = g ? 2*k+1 : 2*k;
        }
        bool g0 = v[1] > v[0];
        float va = g0 ? v[1] : v[0]; int ia = g0 ? ix[1] : ix[0];
        bool g1 = v[3] > v[2];
        float vb = g1 ? v[3] : v[2]; int ib = g1 ? ix[3] : ix[2];
        bool g2 = vb > va;
        float bv = g2 ? vb : va;
        int bi = tid * 8 + (g2 ? ib : ia);

        // warp argmax via REDUX on float bits (dists >= 0 -> u32 monotone)
        unsigned bits = __float_as_uint(bv);
        unsigned wmax = __reduce_max_sync(0xffffffffu, bits);
        unsigned mm   = __ballot_sync(0xffffffffu, bits == wmax);
        int src  = __ffs(mm) - 1;                 // lowest lane = lowest index
        int widx = __shfl_sync(0xffffffffu, bi, src);

        int buf = it & 1;
        if (lane == 0) { sbits[buf][wid] = wmax; sidx[buf][wid] = widx; }
        __syncthreads();

        // every thread scans the 16 warp winners (ascending wid, strict >)
        unsigned fb = sbits[buf][0]; int fi = sidx[buf][0];
#pragma unroll
        for (int w = 1; w < 16; w++) {
            unsigned vb2 = sbits[buf][w];
            if (vb2 > fb) { fb = vb2; fi = sidx[buf][w]; }
        }
        farthest = fi;
    }
}

// ---------------- ball query + compaction + gather --------------------------
// one warp per group (b, s)
// Distance matches the reference's fp32 arithmetic op-for-op:
//   t  = fma-chain dot (GEMM-style, c order 0,1,2)
//   ns = ((cx*cx + cy*cy) + cz*cz)   plain mul/add (elementwise fusion, no FMA)
//   d  = ((-2*t) + ns) + nd          plain mul/add, this association order
__global__ __launch_bounds__(128)
void query_gather_kernel(const float* __restrict__ xyz,
                         const float* __restrict__ pts,
                         const float* __restrict__ newxyz) {
    int gwarp = (blockIdx.x * blockDim.x + threadIdx.x) >> 5;
    int lane  = threadIdx.x & 31;
    int wslot = (threadIdx.x >> 5) & 3;
    int b = gwarp >> 10, s = gwarp & (SS - 1);

    __shared__ int sgidx[4][KK];
    int* gidx = sgidx[wslot];

    const float* bx = xyz + (size_t)b * 3 * NN;
    float cx = newxyz[(size_t)b * 3 * SS + s];
    float cy = newxyz[(size_t)b * 3 * SS + SS + s];
    float cz = newxyz[(size_t)b * 3 * SS + 2 * SS + s];
    float ns = __fadd_rn(__fadd_rn(__fmul_rn(cx, cx), __fmul_rn(cy, cy)),
                         __fmul_rn(cz, cz));

    int cnt = 0;
    for (int j = 0; j < NN / 32; j++) {
        int i = j * 32 + lane;
        float dx = bx[i], dy = bx[NN + i], dz = bx[2 * NN + i];
        float nd = __fadd_rn(__fadd_rn(__fmul_rn(dx, dx), __fmul_rn(dy, dy)),
                             __fmul_rn(dz, dz));
        float t  = __fmaf_rn(cz, dz, __fmaf_rn(cy, dy, __fmul_rn(cx, dx)));
        float d  = __fadd_rn(__fadd_rn(__fmul_rn(-2.0f, t), ns), nd);
        bool ok = !(d > 0.04f);
        unsigned m = __ballot_sync(0xffffffffu, ok);
        int pos = cnt + __popc(m & ((1u << lane) - 1u));
        if (ok && pos < KK) gidx[pos] = i;
        cnt += __popc(m);
        if (cnt >= KK) break;
    }
    int mcnt = min(cnt, KK);
    __syncwarp();

    int base = 0;
    if (lane == 0) {
        base = atomicAdd(&g_ptot, mcnt);
        g_gstart[gwarp] = base;
        g_gcnt[gwarp]   = mcnt;
    }
    base = __shfl_sync(0xffffffffu, base, 0);

    if (lane < mcnt) {
        int i = gidx[lane];
        const float* bp = pts + (size_t)b * 3 * NN;
        float* dst = g_x0 + (size_t)(base + lane) * 8;
        dst[0] = __fsub_rn(bx[i], cx);
        dst[1] = __fsub_rn(bx[NN + i], cy);
        dst[2] = __fsub_rn(bx[2 * NN + i], cz);
        dst[3] = bp[i];
        dst[4] = bp[NN + i];
        dst[5] = bp[2 * NN + i];
        dst[6] = 0.0f;
        dst[7] = 0.0f;
        g_wt[base + lane] = (lane == 0) ? (float)(KK - mcnt + 1) : 1.0f;
    }
}

// ---------------- layer 1: 8(6)->64, raw conv output ------------------------
__global__ __launch_bounds__(128)
void gemm1_kernel(const float* __restrict__ w0) {
    __shared__ float ws[8][64];
    int tid = threadIdx.x;
    for (int idx = tid; idx < 512; idx += 128) {
        int c = idx >> 6, o = idx & 63;
        ws[c][o] = (c < 6) ? w0[o * 6 + c] : 0.0f;
    }
    __syncthreads();
    int ptot = g_ptot;
    for (int p = blockIdx.x * 128 + tid; p < ptot; p += gridDim.x * 128) {
        const float4* xr = (const float4*)(g_x0 + (size_t)p * 8);
        float4 a = xr[0], b4 = xr[1];
        float x[6] = { a.x, a.y, a.z, a.w, b4.x, b4.y };
        float acc[64];
#pragma unroll
        for (int o = 0; o < 64; o++) acc[o] = 0.0f;
#pragma unroll
        for (int c = 0; c < 6; c++)
#pragma unroll
            for (int o = 0; o < 64; o++) acc[o] = fmaf(x[c], ws[c][o], acc[o]);
        float4* out = (float4*)(g_y1 + (size_t)p * 64);
#pragma unroll
        for (int o = 0; o < 16; o++)
            out[o] = make_float4(acc[4*o], acc[4*o+1], acc[4*o+2], acc[4*o+3]);
    }
}

// ---------------- layers 2/3: fused BN+ReLU on input, 64->COUT --------------
template<int COUT, int LAYER_IN>
__global__ __launch_bounds__(128)
void gemm_bn_kernel(const float* __restrict__ W) {
    constexpr int TX = COUT / 8;     // 8 or 16
    constexpr int TY = 128 / TX;     // 16 or 8
    constexpr int PT = 64 / TY;      // 4 or 8 positions per thread

    __shared__ float Xs[64 * 64];        // [pos][c]
    __shared__ float Ws[64 * COUT];      // [c][o]

    const float* Yin  = (LAYER_IN == 0) ? g_y1 : g_y2;
    float*       Yout = (COUT == 64) ? g_y2 : g_y3;
    const float* A  = g_A[LAYER_IN];
    const float* Bc = g_Bc[LAYER_IN];

    int tid = threadIdx.x;
    int tx = tid % TX, ty = tid / TX;

    for (int idx = tid; idx < 64 * COUT; idx += 128) {
        int c = idx & 63, o = idx >> 6;
        Ws[c * COUT + o] = W[o * 64 + c];   // W is (COUT, 64)
    }
    __syncthreads();

    int ptot = g_ptot;
    int ntiles = (ptot + 63) >> 6;
    for (int t = blockIdx.x; t < ntiles; t += gridDim.x) {
        int p0 = t * 64;
        for (int idx = tid; idx < 64 * 64; idx += 128) {
            int c = idx & 63, pl = idx >> 6;
            int p = p0 + pl;
            float v = 0.0f;
            if (p < ptot) {
                float y = Yin[(size_t)p * 64 + c];
                v = fmaxf(fmaf(A[c], y, Bc[c]), 0.0f);
            }
            Xs[pl * 64 + c] = v;
        }
        __syncthreads();

        float acc[PT][8];
#pragma unroll
        for (int j = 0; j < PT; j++)
#pragma unroll
            for (int i = 0; i < 8; i++) acc[j][i] = 0.0f;

#pragma unroll
        for (int c = 0; c < 64; c++) {
            float wv[8], xv[PT];
#pragma unroll
            for (int i = 0; i < 8; i++) wv[i] = Ws[c * COUT + tx + i * TX];
#pragma unroll
            for (int j = 0; j < PT; j++) xv[j] = Xs[(ty * PT + j) * 64 + c];
#pragma unroll
            for (int j = 0; j < PT; j++)
#pragma unroll
                for (int i = 0; i < 8; i++)
                    acc[j][i] = fmaf(xv[j], wv[i], acc[j][i]);
        }

#pragma unroll
        for (int j = 0; j < PT; j++) {
            int p = p0 + ty * PT + j;
            if (p < ptot) {
#pragma unroll
                for (int i = 0; i < 8; i++)
                    Yout[(size_t)p * COUT + tx + i * TX] = acc[j][i];
            }
        }
        __syncthreads();
    }
}

// ---------------- weighted per-channel stats --------------------------------
template<int COUT, int LAYER>
__global__ void stats_kernel() {
    const float* Y = (LAYER == 0) ? g_y1 : (LAYER == 1 ? g_y2 : g_y3);
    int o = threadIdx.x;               // COUT threads
    int ptot = g_ptot;
    double s = 0.0, sq = 0.0;
    int ntiles = (ptot + 255) >> 8;
    for (int t = blockIdx.x; t < ntiles; t += gridDim.x) {
        int pend = min(ptot, t * 256 + 256);
        for (int p = t * 256; p < pend; ++p) {
            float w = g_wt[p];
            float v = Y[(size_t)p * COUT + o];
            float wv = w * v;
            s  += (double)wv;
            sq += (double)(wv * v);
        }
    }
    atomicAdd(&g_sum[LAYER][o], s);
    atomicAdd(&g_sumsq[LAYER][o], sq);
}

// ---------------- finalize BN affine ----------------------------------------
__global__ void finalize_kernel(const float* __restrict__ gamma,
                                const float* __restrict__ beta,
                                int layer, int cout) {
    int o = threadIdx.x;
    if (o >= cout) return;
    double mean = g_sum[layer][o] / TOTAL_DIV;
    double var  = g_sumsq[layer][o] / TOTAL_DIV - mean * mean;
    double inv  = 1.0 / sqrt(var + 1e-5);
    double ga   = (double)gamma[o];
    g_A[layer][o]  = (float)(ga * inv);
    g_Bc[layer][o] = (float)((double)beta[o] - mean * ga * inv);
}

// ---------------- final BN+ReLU + max over group ----------------------------
__global__ __launch_bounds__(128)
void maxpool_kernel(float* __restrict__ feats) {
    int g = blockIdx.x;
    int o = threadIdx.x;               // 128
    int m  = g_gcnt[g];
    int st = g_gstart[g];
    float Aa = g_A[2][o], Bb = g_Bc[2][o];
    float mx = -3.4e38f;
    for (int k = 0; k < m; k++) {
        float y = g_y3[(size_t)(st + k) * 128 + o];
        float z = fmaxf(fmaf(Aa, y, Bb), 0.0f);
        mx = fmaxf(mx, z);
    }
    int b = g >> 10, s = g & (SS - 1);
    feats[((size_t)b * 128 + o) * SS + s] = mx;
}

// ---------------- launch ----------------------------------------------------
extern "C" void kernel_launch(void* const* d_in, const int* in_sizes, int n_in,
                              void* d_out, int out_size) {
    const float* xyz = (const float*)d_in[0];
    const float* pts = (const float*)d_in[1];
    const float* w0  = (const float*)d_in[2];
    const float* g0  = (const float*)d_in[4];
    const float* be0 = (const float*)d_in[5];
    const float* w1  = (const float*)d_in[6];
    const float* g1  = (const float*)d_in[8];
    const float* be1 = (const float*)d_in[9];
    const float* w2  = (const float*)d_in[10];
    const float* g2  = (const float*)d_in[12];
    const float* be2 = (const float*)d_in[13];

    float* out    = (float*)d_out;
    float* newxyz = out;                              // (B,3,S)
    float* feats  = out + (size_t)BB * 3 * SS;        // (B,128,S)

    init_kernel<<<2, 256>>>();
    fps_kernel<<<BB, 512>>>(xyz, newxyz);
    query_gather_kernel<<<GG / 4, 128>>>(xyz, pts, newxyz);

    gemm1_kernel<<<1024, 128>>>(w0);
    stats_kernel<64, 0><<<1024, 64>>>();
    finalize_kernel<<<1, 128>>>(g0, be0, 0, 64);

    gemm_bn_kernel<64, 0><<<2048, 128>>>(w1);
    stats_kernel<64, 1><<<1024, 64>>>();
    finalize_kernel<<<1, 128>>>(g1, be1, 1, 64);

    gemm_bn_kernel<128, 1><<<2048, 128>>>(w2);
    stats_kernel<128, 2><<<1024, 128>>>();
    finalize_kernel<<<1, 128>>>(g2, be2, 2, 128);

    maxpool_kernel<<<GG, 128>>>(feats);
}

// round 6
// speedup vs baseline: 2.6821x; 1.1463x over previous
#include <cuda_runtime.h>
#include <cuda_bf16.h>
#include <math.h>

#define BB 16
#define NN 4096
#define SS 1024
#define KK 32
#define GG (BB*SS)            // 16384 groups
#define MAXP (GG*KK)          // 524288 worst-case positions
#define TOTAL_DIV 524288.0    // BN divisor: B*K*S

// ---------------- scratch (static device globals; no runtime allocation) ----
__device__ float  g_x0[(size_t)MAXP * 8];     // compacted input features (padded to 8 ch)
__device__ float  g_wt[MAXP];                  // multiplicity weight per position
__device__ int    g_gstart[GG];
__device__ int    g_gcnt[GG];
__device__ int    g_ptot;
__device__ float  g_y1[(size_t)MAXP * 64];
__device__ float  g_y2[(size_t)MAXP * 64];
__device__ float  g_y3[(size_t)MAXP * 128];
__device__ double g_sum[3][128];
__device__ double g_sumsq[3][128];
__device__ float  g_A[3][128];
__device__ float  g_Bc[3][128];

// ---------------- packed f32x2 helpers (per-lane .rn semantics == scalar) ---
__device__ __forceinline__ unsigned long long f2_pack(float lo, float hi) {
    unsigned long long r;
    asm("mov.b64 %0, {%1, %2};" : "=l"(r) : "f"(lo), "f"(hi));
    return r;
}
__device__ __forceinline__ void f2_unpack(unsigned long long v, float& lo, float& hi) {
    asm("mov.b64 {%0, %1}, %2;" : "=f"(lo), "=f"(hi) : "l"(v));
}
__device__ __forceinline__ unsigned long long f2_add(unsigned long long a, unsigned long long b) {
    unsigned long long r;
    asm("add.rn.f32x2 %0, %1, %2;" : "=l"(r) : "l"(a), "l"(b));
    return r;
}
__device__ __forceinline__ unsigned long long f2_mul(unsigned long long a, unsigned long long b) {
    unsigned long long r;
    asm("mul.rn.f32x2 %0, %1, %2;" : "=l"(r) : "l"(a), "l"(b));
    return r;
}

// ---------------- init ------------------------------------------------------
__global__ void init_kernel() {
    int t = blockIdx.x * blockDim.x + threadIdx.x;
    if (t == 0) g_ptot = 0;
    if (t < 384) {
        ((double*)g_sum)[t]   = 0.0;
        ((double*)g_sumsq)[t] = 0.0;
    }
}

// ---------------- farthest point sampling (bit-exact) -----------------------
// one block per batch, 512 threads, 8 points/thread (4 f32x2 pairs).
// Per iteration:
//   packed dist update -> local sel-tree argmax -> warp REDUX argmax ->
//   leaders STS (bits,widx) -> ONE barrier ->
//   block winner via second REDUX: every lane loads entry (lane&15),
//   redux.max -> ballot(==max) -> ffs = lowest wid (first-index tiebreak) ->
//   broadcast LDS of the winning index.
__global__ __launch_bounds__(512, 1)
void fps_kernel(const float* __restrict__ xyz, float* __restrict__ newxyz) {
    int b = blockIdx.x, tid = threadIdx.x;
    const float* bx = xyz + (size_t)b * 3 * NN;

    unsigned long long px2[4], py2[4], pz2[4];
    float dist[8];
    {
        const float4* x4 = (const float4*)(bx);
        const float4* y4 = (const float4*)(bx + NN);
        const float4* z4 = (const float4*)(bx + 2 * NN);
#pragma unroll
        for (int h = 0; h < 2; h++) {
            float4 xa = x4[tid * 2 + h], ya = y4[tid * 2 + h], za = z4[tid * 2 + h];
            px2[2*h]   = f2_pack(xa.x, xa.y);
            px2[2*h+1] = f2_pack(xa.z, xa.w);
            py2[2*h]   = f2_pack(ya.x, ya.y);
            py2[2*h+1] = f2_pack(ya.z, ya.w);
            pz2[2*h]   = f2_pack(za.x, za.y);
            pz2[2*h+1] = f2_pack(za.z, za.w);
        }
    }
#pragma unroll
    for (int j = 0; j < 8; j++) dist[j] = 1e10f;

    __shared__ unsigned sbits[2][16];
    __shared__ int      sidx[2][16];
    int lane = tid & 31, wid = tid >> 5;
    int farthest = 0;

    for (int it = 0; it < SS; ++it) {
        float cx = __ldg(bx + farthest);
        float cy = __ldg(bx + NN + farthest);
        float cz = __ldg(bx + 2 * NN + farthest);
        if (tid == 0) {
            newxyz[(size_t)b * 3 * SS + it]          = cx;
            newxyz[(size_t)b * 3 * SS + SS + it]     = cy;
            newxyz[(size_t)b * 3 * SS + 2 * SS + it] = cz;
        }
        unsigned long long ncx = f2_pack(-cx, -cx);
        unsigned long long ncy = f2_pack(-cy, -cy);
        unsigned long long ncz = f2_pack(-cz, -cz);

        // packed distance update: per lane rn(sub), rn(mul), rn((xx+yy)+zz)
#pragma unroll
        for (int k = 0; k < 4; k++) {
            unsigned long long dx = f2_add(px2[k], ncx);
            unsigned long long dy = f2_add(py2[k], ncy);
            unsigned long long dz = f2_add(pz2[k], ncz);
            unsigned long long s  = f2_add(f2_add(f2_mul(dx, dx), f2_mul(dy, dy)),
                                           f2_mul(dz, dz));
            float d0, d1;
            f2_unpack(s, d0, d1);
            dist[2*k]   = fminf(dist[2*k],   d0);
            dist[2*k+1] = fminf(dist[2*k+1], d1);
        }

        // local argmax tree over 8, first-index ties (b>a keeps lower index)
        float v[4]; int ix[4];
#pragma unroll
        for (int k = 0; k < 4; k++) {
            bool g = dist[2*k+1] > dist[2*k];
            v[k]  = g ? dist[2*k+1] : dist[2*k];
            ix[k] = g ? 2*k+1 : 2*k;
        }
        bool g0 = v[1] > v[0];
        float va = g0 ? v[1] : v[0]; int ia = g0 ? ix[1] : ix[0];
        bool g1 = v[3] > v[2];
        float vb = g1 ? v[3] : v[2]; int ib = g1 ? ix[3] : ix[2];
        bool g2 = vb > va;
        float bv = g2 ? vb : va;
        int bi = tid * 8 + (g2 ? ib : ia);

        // warp argmax via REDUX on float bits (dists >= 0 -> u32 monotone)
        unsigned bits = __float_as_uint(bv);
        unsigned wmax = __reduce_max_sync(0xffffffffu, bits);
        unsigned mm   = __ballot_sync(0xffffffffu, bits == wmax);
        int src  = __ffs(mm) - 1;                 // lowest lane = lowest index
        int widx = __shfl_sync(0xffffffffu, bi, src);

        int buf = it & 1;
        if (lane == 0) { sbits[buf][wid] = wmax; sidx[buf][wid] = widx; }
        __syncthreads();

        // block argmax via second REDUX over the 16 warp winners.
        // lanes 16-31 duplicate entries 0-15; ffs of the ballot still yields
        // the lowest wid => first-index tiebreak identical to a linear scan.
        unsigned eb   = sbits[buf][lane & 15];
        unsigned bmax = __reduce_max_sync(0xffffffffu, eb);
        unsigned wm   = __ballot_sync(0xffffffffu, eb == bmax);
        int fw = (__ffs(wm) - 1) & 15;
        farthest = sidx[buf][fw];
    }
}

// ---------------- ball query + compaction + gather --------------------------
// one warp per group (b, s)
// Distance matches the reference's fp32 arithmetic op-for-op:
//   t  = fma-chain dot (GEMM-style, c order 0,1,2)
//   ns = ((cx*cx + cy*cy) + cz*cz)   plain mul/add (elementwise fusion, no FMA)
//   d  = ((-2*t) + ns) + nd          plain mul/add, this association order
__global__ __launch_bounds__(128)
void query_gather_kernel(const float* __restrict__ xyz,
                         const float* __restrict__ pts,
                         const float* __restrict__ newxyz) {
    int gwarp = (blockIdx.x * blockDim.x + threadIdx.x) >> 5;
    int lane  = threadIdx.x & 31;
    int wslot = (threadIdx.x >> 5) & 3;
    int b = gwarp >> 10, s = gwarp & (SS - 1);

    __shared__ int sgidx[4][KK];
    int* gidx = sgidx[wslot];

    const float* bx = xyz + (size_t)b * 3 * NN;
    float cx = newxyz[(size_t)b * 3 * SS + s];
    float cy = newxyz[(size_t)b * 3 * SS + SS + s];
    float cz = newxyz[(size_t)b * 3 * SS + 2 * SS + s];
    float ns = __fadd_rn(__fadd_rn(__fmul_rn(cx, cx), __fmul_rn(cy, cy)),
                         __fmul_rn(cz, cz));

    int cnt = 0;
    for (int j = 0; j < NN / 32; j++) {
        int i = j * 32 + lane;
        float dx = bx[i], dy = bx[NN + i], dz = bx[2 * NN + i];
        float nd = __fadd_rn(__fadd_rn(__fmul_rn(dx, dx), __fmul_rn(dy, dy)),
                             __fmul_rn(dz, dz));
        float t  = __fmaf_rn(cz, dz, __fmaf_rn(cy, dy, __fmul_rn(cx, dx)));
        float d  = __fadd_rn(__fadd_rn(__fmul_rn(-2.0f, t), ns), nd);
        bool ok = !(d > 0.04f);
        unsigned m = __ballot_sync(0xffffffffu, ok);
        int pos = cnt + __popc(m & ((1u << lane) - 1u));
        if (ok && pos < KK) gidx[pos] = i;
        cnt += __popc(m);
        if (cnt >= KK) break;
    }
    int mcnt = min(cnt, KK);
    __syncwarp();

    int base = 0;
    if (lane == 0) {
        base = atomicAdd(&g_ptot, mcnt);
        g_gstart[gwarp] = base;
        g_gcnt[gwarp]   = mcnt;
    }
    base = __shfl_sync(0xffffffffu, base, 0);

    if (lane < mcnt) {
        int i = gidx[lane];
        const float* bp = pts + (size_t)b * 3 * NN;
        float* dst = g_x0 + (size_t)(base + lane) * 8;
        dst[0] = __fsub_rn(bx[i], cx);
        dst[1] = __fsub_rn(bx[NN + i], cy);
        dst[2] = __fsub_rn(bx[2 * NN + i], cz);
        dst[3] = bp[i];
        dst[4] = bp[NN + i];
        dst[5] = bp[2 * NN + i];
        dst[6] = 0.0f;
        dst[7] = 0.0f;
        g_wt[base + lane] = (lane == 0) ? (float)(KK - mcnt + 1) : 1.0f;
    }
}

// ---------------- layer 1: 8(6)->64, raw conv output ------------------------
__global__ __launch_bounds__(128)
void gemm1_kernel(const float* __restrict__ w0) {
    __shared__ float ws[8][64];
    int tid = threadIdx.x;
    for (int idx = tid; idx < 512; idx += 128) {
        int c = idx >> 6, o = idx & 63;
        ws[c][o] = (c < 6) ? w0[o * 6 + c] : 0.0f;
    }
    __syncthreads();
    int ptot = g_ptot;
    for (int p = blockIdx.x * 128 + tid; p < ptot; p += gridDim.x * 128) {
        const float4* xr = (const float4*)(g_x0 + (size_t)p * 8);
        float4 a = xr[0], b4 = xr[1];
        float x[6] = { a.x, a.y, a.z, a.w, b4.x, b4.y };
        float acc[64];
#pragma unroll
        for (int o = 0; o < 64; o++) acc[o] = 0.0f;
#pragma unroll
        for (int c = 0; c < 6; c++)
#pragma unroll
            for (int o = 0; o < 64; o++) acc[o] = fmaf(x[c], ws[c][o], acc[o]);
        float4* out = (float4*)(g_y1 + (size_t)p * 64);
#pragma unroll
        for (int o = 0; o < 16; o++)
            out[o] = make_float4(acc[4*o], acc[4*o+1], acc[4*o+2], acc[4*o+3]);
    }
}

// ---------------- layers 2/3: fused BN+ReLU on input, 64->COUT --------------
template<int COUT, int LAYER_IN>
__global__ __launch_bounds__(128)
void gemm_bn_kernel(const float* __restrict__ W) {
    constexpr int TX = COUT / 8;     // 8 or 16
    constexpr int TY = 128 / TX;     // 16 or 8
    constexpr int PT = 64 / TY;      // 4 or 8 positions per thread

    __shared__ float Xs[64 * 64];        // [pos][c]
    __shared__ float Ws[64 * COUT];      // [c][o]

    const float* Yin  = (LAYER_IN == 0) ? g_y1 : g_y2;
    float*       Yout = (COUT == 64) ? g_y2 : g_y3;
    const float* A  = g_A[LAYER_IN];
    const float* Bc = g_Bc[LAYER_IN];

    int tid = threadIdx.x;
    int tx = tid % TX, ty = tid / TX;

    for (int idx = tid; idx < 64 * COUT; idx += 128) {
        int c = idx & 63, o = idx >> 6;
        Ws[c * COUT + o] = W[o * 64 + c];   // W is (COUT, 64)
    }
    __syncthreads();

    int ptot = g_ptot;
    int ntiles = (ptot + 63) >> 6;
    for (int t = blockIdx.x; t < ntiles; t += gridDim.x) {
        int p0 = t * 64;
        for (int idx = tid; idx < 64 * 64; idx += 128) {
            int c = idx & 63, pl = idx >> 6;
            int p = p0 + pl;
            float v = 0.0f;
            if (p < ptot) {
                float y = Yin[(size_t)p * 64 + c];
                v = fmaxf(fmaf(A[c], y, Bc[c]), 0.0f);
            }
            Xs[pl * 64 + c] = v;
        }
        __syncthreads();

        float acc[PT][8];
#pragma unroll
        for (int j = 0; j < PT; j++)
#pragma unroll
            for (int i = 0; i < 8; i++) acc[j][i] = 0.0f;

#pragma unroll
        for (int c = 0; c < 64; c++) {
            float wv[8], xv[PT];
#pragma unroll
            for (int i = 0; i < 8; i++) wv[i] = Ws[c * COUT + tx + i * TX];
#pragma unroll
            for (int j = 0; j < PT; j++) xv[j] = Xs[(ty * PT + j) * 64 + c];
#pragma unroll
            for (int j = 0; j < PT; j++)
#pragma unroll
                for (int i = 0; i < 8; i++)
                    acc[j][i] = fmaf(xv[j], wv[i], acc[j][i]);
        }

#pragma unroll
        for (int j = 0; j < PT; j++) {
            int p = p0 + ty * PT + j;
            if (p < ptot) {
#pragma unroll
                for (int i = 0; i < 8; i++)
                    Yout[(size_t)p * COUT + tx + i * TX] = acc[j][i];
            }
        }
        __syncthreads();
    }
}

// ---------------- weighted per-channel stats --------------------------------
template<int COUT, int LAYER>
__global__ void stats_kernel() {
    const float* Y = (LAYER == 0) ? g_y1 : (LAYER == 1 ? g_y2 : g_y3);
    int o = threadIdx.x;               // COUT threads
    int ptot = g_ptot;
    double s = 0.0, sq = 0.0;
    int ntiles = (ptot + 255) >> 8;
    for (int t = blockIdx.x; t < ntiles; t += gridDim.x) {
        int pend = min(ptot, t * 256 + 256);
        for (int p = t * 256; p < pend; ++p) {
            float w = g_wt[p];
            float v = Y[(size_t)p * COUT + o];
            float wv = w * v;
            s  += (double)wv;
            sq += (double)(wv * v);
        }
    }
    atomicAdd(&g_sum[LAYER][o], s);
    atomicAdd(&g_sumsq[LAYER][o], sq);
}

// ---------------- finalize BN affine ----------------------------------------
__global__ void finalize_kernel(const float* __restrict__ gamma,
                                const float* __restrict__ beta,
                                int layer, int cout) {
    int o = threadIdx.x;
    if (o >= cout) return;
    double mean = g_sum[layer][o] / TOTAL_DIV;
    double var  = g_sumsq[layer][o] / TOTAL_DIV - mean * mean;
    double inv  = 1.0 / sqrt(var + 1e-5);
    double ga   = (double)gamma[o];
    g_A[layer][o]  = (float)(ga * inv);
    g_Bc[layer][o] = (float)((double)beta[o] - mean * ga * inv);
}

// ---------------- final BN+ReLU + max over group ----------------------------
__global__ __launch_bounds__(128)
void maxpool_kernel(float* __restrict__ feats) {
    int g = blockIdx.x;
    int o = threadIdx.x;               // 128
    int m  = g_gcnt[g];
    int st = g_gstart[g];
    float Aa = g_A[2][o], Bb = g_Bc[2][o];
    float mx = -3.4e38f;
    for (int k = 0; k < m; k++) {
        float y = g_y3[(size_t)(st + k) * 128 + o];
        float z = fmaxf(fmaf(Aa, y, Bb), 0.0f);
        mx = fmaxf(mx, z);
    }
    int b = g >> 10, s = g & (SS - 1);
    feats[((size_t)b * 128 + o) * SS + s] = mx;
}

// ---------------- launch ----------------------------------------------------
extern "C" void kernel_launch(void* const* d_in, const int* in_sizes, int n_in,
                              void* d_out, int out_size) {
    const float* xyz = (const float*)d_in[0];
    const float* pts = (const float*)d_in[1];
    const float* w0  = (const float*)d_in[2];
    const float* g0  = (const float*)d_in[4];
    const float* be0 = (const float*)d_in[5];
    const float* w1  = (const float*)d_in[6];
    const float* g1  = (const float*)d_in[8];
    const float* be1 = (const float*)d_in[9];
    const float* w2  = (const float*)d_in[10];
    const float* g2  = (const float*)d_in[12];
    const float* be2 = (const float*)d_in[13];

    float* out    = (float*)d_out;
    float* newxyz = out;                              // (B,3,S)
    float* feats  = out + (size_t)BB * 3 * SS;        // (B,128,S)

    init_kernel<<<2, 256>>>();
    fps_kernel<<<BB, 512>>>(xyz, newxyz);
    query_gather_kernel<<<GG / 4, 128>>>(xyz, pts, newxyz);

    gemm1_kernel<<<1024, 128>>>(w0);
    stats_kernel<64, 0><<<1024, 64>>>();
    finalize_kernel<<<1, 128>>>(g0, be0, 0, 64);

    gemm_bn_kernel<64, 0><<<2048, 128>>>(w1);
    stats_kernel<64, 1><<<1024, 64>>>();
    finalize_kernel<<<1, 128>>>(g1, be1, 1, 64);

    gemm_bn_kernel<128, 1><<<2048, 128>>>(w2);
    stats_kernel<128, 2><<<1024, 128>>>();
    finalize_kernel<<<1, 128>>>(g2, be2, 2, 128);

    maxpool_kernel<<<GG, 128>>>(feats);
}

// round 9
// speedup vs baseline: 3.7812x; 1.4098x over previous
#include <cuda_runtime.h>
#include <cuda_bf16.h>
#include <math.h>

#define BB 16
#define NN 4096
#define SS 1024
#define KK 32
#define GG (BB*SS)            // 16384 groups
#define MAXP (GG*KK)          // 524288 worst-case positions
#define TOTAL_DIV 524288.0    // BN divisor: B*K*S

// ---------------- scratch (static device globals; no runtime allocation) ----
__device__ float  g_x0[(size_t)MAXP * 8];     // compacted input features (padded to 8 ch)
__device__ float  g_wt[MAXP];                  // multiplicity weight per position
__device__ int    g_gstart[GG];
__device__ int    g_gcnt[GG];
__device__ int    g_ptot;
__device__ float  g_y1[(size_t)MAXP * 64];
__device__ float  g_y2[(size_t)MAXP * 64];
__device__ float  g_y3[(size_t)MAXP * 128];
__device__ double g_sum[3][128];
__device__ double g_sumsq[3][128];
__device__ float  g_A[3][128];
__device__ float  g_Bc[3][128];

// ---------------- packed f32x2 helpers (per-lane .rn semantics == scalar) ---
__device__ __forceinline__ unsigned long long f2_pack(float lo, float hi) {
    unsigned long long r;
    asm("mov.b64 %0, {%1, %2};" : "=l"(r) : "f"(lo), "f"(hi));
    return r;
}
__device__ __forceinline__ void f2_unpack(unsigned long long v, float& lo, float& hi) {
    asm("mov.b64 {%0, %1}, %2;" : "=f"(lo), "=f"(hi) : "l"(v));
}
__device__ __forceinline__ unsigned long long f2_add(unsigned long long a, unsigned long long b) {
    unsigned long long r;
    asm("add.rn.f32x2 %0, %1, %2;" : "=l"(r) : "l"(a), "l"(b));
    return r;
}
__device__ __forceinline__ unsigned long long f2_mul(unsigned long long a, unsigned long long b) {
    unsigned long long r;
    asm("mul.rn.f32x2 %0, %1, %2;" : "=l"(r) : "l"(a), "l"(b));
    return r;
}

// ---------------- init ------------------------------------------------------
__global__ void init_kernel() {
    int t = blockIdx.x * blockDim.x + threadIdx.x;
    if (t == 0) g_ptot = 0;
    if (t < 384) {
        ((double*)g_sum)[t]   = 0.0;
        ((double*)g_sumsq)[t] = 0.0;
    }
}

// ---------------- farthest point sampling (bit-exact) -----------------------
// one block per batch, 512 threads, 8 points/thread (4 f32x2 pairs).
// Winning indices recorded in smem history; centroids written in bulk at end
// (keeps STG + addressing off the per-iteration critical path).
__global__ __launch_bounds__(512, 1)
void fps_kernel(const float* __restrict__ xyz, float* __restrict__ newxyz) {
    int b = blockIdx.x, tid = threadIdx.x;
    const float* bx = xyz + (size_t)b * 3 * NN;

    unsigned long long px2[4], py2[4], pz2[4];
    float dist[8];
    {
        const float4* x4 = (const float4*)(bx);
        const float4* y4 = (const float4*)(bx + NN);
        const float4* z4 = (const float4*)(bx + 2 * NN);
#pragma unroll
        for (int h = 0; h < 2; h++) {
            float4 xa = x4[tid * 2 + h], ya = y4[tid * 2 + h], za = z4[tid * 2 + h];
            px2[2*h]   = f2_pack(xa.x, xa.y);
            px2[2*h+1] = f2_pack(xa.z, xa.w);
            py2[2*h]   = f2_pack(ya.x, ya.y);
            py2[2*h+1] = f2_pack(ya.z, ya.w);
            pz2[2*h]   = f2_pack(za.x, za.y);
            pz2[2*h+1] = f2_pack(za.z, za.w);
        }
    }
#pragma unroll
    for (int j = 0; j < 8; j++) dist[j] = 1e10f;

    __shared__ unsigned long long skey[2][16];   // {bits<<32 | widx} per warp
    __shared__ int fhist[SS];
    int lane = tid & 31, wid = tid >> 5;
    int farthest = 0;

    for (int it = 0; it < SS; ++it) {
        if (tid == 0) fhist[it] = farthest;
        float cx = __ldg(bx + farthest);
        float cy = __ldg(bx + NN + farthest);
        float cz = __ldg(bx + 2 * NN + farthest);
        unsigned long long ncx = f2_pack(-cx, -cx);
        unsigned long long ncy = f2_pack(-cy, -cy);
        unsigned long long ncz = f2_pack(-cz, -cz);

        // packed distance update: per lane rn(sub), rn(mul), rn((xx+yy)+zz)
#pragma unroll
        for (int k = 0; k < 4; k++) {
            unsigned long long dx = f2_add(px2[k], ncx);
            unsigned long long dy = f2_add(py2[k], ncy);
            unsigned long long dz = f2_add(pz2[k], ncz);
            unsigned long long s  = f2_add(f2_add(f2_mul(dx, dx), f2_mul(dy, dy)),
                                           f2_mul(dz, dz));
            float d0, d1;
            f2_unpack(s, d0, d1);
            dist[2*k]   = fminf(dist[2*k],   d0);
            dist[2*k+1] = fminf(dist[2*k+1], d1);
        }

        // local argmax tree over 8, first-index ties (b>a keeps lower index)
        float v[4]; int ix[4];
#pragma unroll
        for (int k = 0; k < 4; k++) {
            bool g = dist[2*k+1] > dist[2*k];
            v[k]  = g ? dist[2*k+1] : dist[2*k];
            ix[k] = g ? 2*k+1 : 2*k;
        }
        bool g0 = v[1] > v[0];
        float va = g0 ? v[1] : v[0]; int ia = g0 ? ix[1] : ix[0];
        bool g1 = v[3] > v[2];
        float vb = g1 ? v[3] : v[2]; int ib = g1 ? ix[3] : ix[2];
        bool g2 = vb > va;
        float bv = g2 ? vb : va;
        int bi = tid * 8 + (g2 ? ib : ia);

        // warp argmax via REDUX on float bits (dists >= 0 -> u32 monotone)
        unsigned bits = __float_as_uint(bv);
        unsigned wmax = __reduce_max_sync(0xffffffffu, bits);
        unsigned mm   = __ballot_sync(0xffffffffu, bits == wmax);
        int src  = __ffs(mm) - 1;                 // lowest lane = lowest index
        int widx = __shfl_sync(0xffffffffu, bi, src);

        int buf = it & 1;
        if (lane == 0)
            skey[buf][wid] = ((unsigned long long)wmax << 32) | (unsigned)widx;
        __syncthreads();

        // block argmax: lane loads entry (lane&15); redux on high word;
        // ballot+ffs -> lowest wid (first-index tiebreak); shfl the low word.
        unsigned long long e = skey[buf][lane & 15];
        unsigned eb   = (unsigned)(e >> 32);
        int      ei   = (int)(unsigned)e;
        unsigned bmax = __reduce_max_sync(0xffffffffu, eb);
        unsigned wm   = __ballot_sync(0xffffffffu, eb == bmax);
        int fl = __ffs(wm) - 1;
        farthest = __shfl_sync(0xffffffffu, ei, fl);
    }

    // bulk centroid write-out
    __syncthreads();
    for (int i = tid; i < SS; i += 512) {
        int idx = fhist[i];
        newxyz[(size_t)b * 3 * SS + i]          = __ldg(bx + idx);
        newxyz[(size_t)b * 3 * SS + SS + i]     = __ldg(bx + NN + idx);
        newxyz[(size_t)b * 3 * SS + 2 * SS + i] = __ldg(bx + 2 * NN + idx);
    }
}

// ---------------- ball query + compaction + gather --------------------------
// one warp per group (b, s)
// Distance matches the reference's fp32 arithmetic op-for-op:
//   t  = fma-chain dot (GEMM-style, c order 0,1,2)
//   ns = ((cx*cx + cy*cy) + cz*cz)   plain mul/add (elementwise fusion, no FMA)
//   d  = ((-2*t) + ns) + nd          plain mul/add, this association order
__global__ __launch_bounds__(128)
void query_gather_kernel(const float* __restrict__ xyz,
                         const float* __restrict__ pts,
                         const float* __restrict__ newxyz) {
    int gwarp = (blockIdx.x * blockDim.x + threadIdx.x) >> 5;
    int lane  = threadIdx.x & 31;
    int wslot = (threadIdx.x >> 5) & 3;
    int b = gwarp >> 10, s = gwarp & (SS - 1);

    __shared__ int sgidx[4][KK];
    int* gidx = sgidx[wslot];

    const float* bx = xyz + (size_t)b * 3 * NN;
    float cx = newxyz[(size_t)b * 3 * SS + s];
    float cy = newxyz[(size_t)b * 3 * SS + SS + s];
    float cz = newxyz[(size_t)b * 3 * SS + 2 * SS + s];
    float ns = __fadd_rn(__fadd_rn(__fmul_rn(cx, cx), __fmul_rn(cy, cy)),
                         __fmul_rn(cz, cz));

    int cnt = 0;
    for (int j = 0; j < NN / 32; j++) {
        int i = j * 32 + lane;
        float dx = bx[i], dy = bx[NN + i], dz = bx[2 * NN + i];
        float nd = __fadd_rn(__fadd_rn(__fmul_rn(dx, dx), __fmul_rn(dy, dy)),
                             __fmul_rn(dz, dz));
        float t  = __fmaf_rn(cz, dz, __fmaf_rn(cy, dy, __fmul_rn(cx, dx)));
        float d  = __fadd_rn(__fadd_rn(__fmul_rn(-2.0f, t), ns), nd);
        bool ok = !(d > 0.04f);
        unsigned m = __ballot_sync(0xffffffffu, ok);
        int pos = cnt + __popc(m & ((1u << lane) - 1u));
        if (ok && pos < KK) gidx[pos] = i;
        cnt += __popc(m);
        if (cnt >= KK) break;
    }
    int mcnt = min(cnt, KK);
    __syncwarp();

    int base = 0;
    if (lane == 0) {
        base = atomicAdd(&g_ptot, mcnt);
        g_gstart[gwarp] = base;
        g_gcnt[gwarp]   = mcnt;
    }
    base = __shfl_sync(0xffffffffu, base, 0);

    if (lane < mcnt) {
        int i = gidx[lane];
        const float* bp = pts + (size_t)b * 3 * NN;
        float* dst = g_x0 + (size_t)(base + lane) * 8;
        dst[0] = __fsub_rn(bx[i], cx);
        dst[1] = __fsub_rn(bx[NN + i], cy);
        dst[2] = __fsub_rn(bx[2 * NN + i], cz);
        dst[3] = bp[i];
        dst[4] = bp[NN + i];
        dst[5] = bp[2 * NN + i];
        dst[6] = 0.0f;
        dst[7] = 0.0f;
        g_wt[base + lane] = (lane == 0) ? (float)(KK - mcnt + 1) : 1.0f;
    }
}

// ---------------- unified GEMM + fused output stats --------------------------
// CIN: input channels (8 padded, or 64). COUT: 64 or 128.
// LOUT: 0 -> x0->y1 (raw input), 1 -> y1->y2 (BN+ReLU in), 2 -> y2->y3.
// Epilogue: weighted per-channel sum/sumsq partials (float per thread),
// block-reduced via smem float atomics, one double atomicAdd per ch per block.
template<int CIN, int COUT, int LOUT>
__global__ __launch_bounds__(128)
void gemm_stats_kernel(const float* __restrict__ W) {
    constexpr bool BN_IN = (LOUT > 0);
    constexpr int TX = COUT / 8;     // 8 or 16
    constexpr int TY = 128 / TX;     // 16 or 8
    constexpr int PT = 64 / TY;      // 4 or 8 positions per thread

    __shared__ float Xs[64 * CIN];
    __shared__ float Ws[CIN * COUT];
    __shared__ float ssum[COUT], ssq[COUT];

    const float* Yin  = (LOUT == 0) ? g_x0 : (LOUT == 1 ? g_y1 : g_y2);
    float*       Yout = (LOUT == 0) ? g_y1 : (LOUT == 1 ? g_y2 : g_y3);
    const float* A  = g_A[BN_IN ? LOUT - 1 : 0];
    const float* Bc = g_Bc[BN_IN ? LOUT - 1 : 0];

    int tid = threadIdx.x;
    int tx = tid % TX, ty = tid / TX;

    for (int idx = tid; idx < CIN * COUT; idx += 128) {
        int c = idx % CIN, o = idx / CIN;
        float w;
        if (LOUT == 0) w = (c < 6) ? W[o * 6 + c] : 0.0f;   // W is (64, 6)
        else           w = W[o * 64 + c];                    // W is (COUT, 64)
        Ws[c * COUT + o] = w;
    }
    if (tid < COUT) { ssum[tid] = 0.0f; ssq[tid] = 0.0f; }
    __syncthreads();

    float ps[8], pq[8];
#pragma unroll
    for (int i = 0; i < 8; i++) { ps[i] = 0.0f; pq[i] = 0.0f; }

    int ptot = g_ptot;
    int ntiles = (ptot + 63) >> 6;
    for (int t = blockIdx.x; t < ntiles; t += gridDim.x) {
        int p0 = t * 64;
        for (int idx = tid; idx < 64 * CIN; idx += 128) {
            int c = idx % CIN, pl = idx / CIN;
            int p = p0 + pl;
            float v = 0.0f;
            if (p < ptot) {
                float y = Yin[(size_t)p * CIN + c];
                v = BN_IN ? fmaxf(fmaf(A[c], y, Bc[c]), 0.0f) : y;
            }
            Xs[pl * CIN + c] = v;
        }
        __syncthreads();

        float acc[PT][8];
#pragma unroll
        for (int j = 0; j < PT; j++)
#pragma unroll
            for (int i = 0; i < 8; i++) acc[j][i] = 0.0f;

#pragma unroll
        for (int c = 0; c < CIN; c++) {
            float wv[8], xv[PT];
#pragma unroll
            for (int i = 0; i < 8; i++) wv[i] = Ws[c * COUT + tx + i * TX];
#pragma unroll
            for (int j = 0; j < PT; j++) xv[j] = Xs[(ty * PT + j) * CIN + c];
#pragma unroll
            for (int j = 0; j < PT; j++)
#pragma unroll
                for (int i = 0; i < 8; i++)
                    acc[j][i] = fmaf(xv[j], wv[i], acc[j][i]);
        }

#pragma unroll
        for (int j = 0; j < PT; j++) {
            int p = p0 + ty * PT + j;
            if (p < ptot) {
                float w = g_wt[p];
#pragma unroll
                for (int i = 0; i < 8; i++) {
                    float v = acc[j][i];
                    Yout[(size_t)p * COUT + tx + i * TX] = v;
                    float wv = w * v;
                    ps[i] += wv;
                    pq[i] += wv * v;
                }
            }
        }
        __syncthreads();
    }

    // block-level stats reduction
#pragma unroll
    for (int i = 0; i < 8; i++) {
        atomicAdd(&ssum[tx + i * TX], ps[i]);
        atomicAdd(&ssq[tx + i * TX],  pq[i]);
    }
    __syncthreads();
    if (tid < COUT) {
        atomicAdd(&g_sum[LOUT][tid],   (double)ssum[tid]);
        atomicAdd(&g_sumsq[LOUT][tid], (double)ssq[tid]);
    }
}

// ---------------- finalize BN affine ----------------------------------------
__global__ void finalize_kernel(const float* __restrict__ gamma,
                                const float* __restrict__ beta,
                                int layer, int cout) {
    int o = threadIdx.x;
    if (o >= cout) return;
    double mean = g_sum[layer][o] / TOTAL_DIV;
    double var  = g_sumsq[layer][o] / TOTAL_DIV - mean * mean;
    double inv  = 1.0 / sqrt(var + 1e-5);
    double ga   = (double)gamma[o];
    g_A[layer][o]  = (float)(ga * inv);
    g_Bc[layer][o] = (float)((double)beta[o] - mean * ga * inv);
}

// ---------------- final BN+ReLU + max over group ----------------------------
__global__ __launch_bounds__(128)
void maxpool_kernel(float* __restrict__ feats) {
    int g = blockIdx.x;
    int o = threadIdx.x;               // 128
    int m  = g_gcnt[g];
    int st = g_gstart[g];
    float Aa = g_A[2][o], Bb = g_Bc[2][o];
    float mx = -3.4e38f;
    for (int k = 0; k < m; k++) {
        float y = g_y3[(size_t)(st + k) * 128 + o];
        float z = fmaxf(fmaf(Aa, y, Bb), 0.0f);
        mx = fmaxf(mx, z);
    }
    int b = g >> 10, s = g & (SS - 1);
    feats[((size_t)b * 128 + o) * SS + s] = mx;
}

// ---------------- launch ----------------------------------------------------
extern "C" void kernel_launch(void* const* d_in, const int* in_sizes, int n_in,
                              void* d_out, int out_size) {
    const float* xyz = (const float*)d_in[0];
    const float* pts = (const float*)d_in[1];
    const float* w0  = (const float*)d_in[2];
    const float* g0  = (const float*)d_in[4];
    const float* be0 = (const float*)d_in[5];
    const float* w1  = (const float*)d_in[6];
    const float* g1  = (const float*)d_in[8];
    const float* be1 = (const float*)d_in[9];
    const float* w2  = (const float*)d_in[10];
    const float* g2  = (const float*)d_in[12];
    const float* be2 = (const float*)d_in[13];

    float* out    = (float*)d_out;
    float* newxyz = out;                              // (B,3,S)
    float* feats  = out + (size_t)BB * 3 * SS;        // (B,128,S)

    init_kernel<<<2, 256>>>();
    fps_kernel<<<BB, 512>>>(xyz, newxyz);
    query_gather_kernel<<<GG / 4, 128>>>(xyz, pts, newxyz);

    gemm_stats_kernel<8, 64, 0><<<1024, 128>>>(w0);
    finalize_kernel<<<1, 128>>>(g0, be0, 0, 64);

    gemm_stats_kernel<64, 64, 1><<<1024, 128>>>(w1);
    finalize_kernel<<<1, 128>>>(g1, be1, 1, 64);

    gemm_stats_kernel<64, 128, 2><<<1024, 128>>>(w2);
    finalize_kernel<<<1, 128>>>(g2, be2, 2, 128);

    maxpool_kernel<<<GG, 128>>>(feats);
}

// round 10
// speedup vs baseline: 3.8471x; 1.0174x over previous
#include <cuda_runtime.h>
#include <cuda_bf16.h>
#include <math.h>

#define BB 16
#define NN 4096
#define SS 1024
#define KK 32
#define GG (BB*SS)            // 16384 groups
#define MAXP (GG*KK)          // 524288 worst-case positions
#define TOTAL_DIV 524288.0    // BN divisor: B*K*S

// ---------------- scratch (static device globals; no runtime allocation) ----
__device__ float  g_x0[(size_t)MAXP * 8];     // compacted input features (padded to 8 ch)
__device__ float  g_wt[MAXP];                  // multiplicity weight per position
__device__ int    g_gstart[GG];
__device__ int    g_gcnt[GG];
__device__ int    g_ptot;
__device__ float  g_y1[(size_t)MAXP * 64];
__device__ float  g_y2[(size_t)MAXP * 64];
__device__ float  g_y3[(size_t)MAXP * 128];
__device__ double g_sum[3][128];
__device__ double g_sumsq[3][128];
__device__ float  g_A[3][128];
__device__ float  g_Bc[3][128];

// ---------------- packed f32x2 helpers (per-lane .rn semantics == scalar) ---
__device__ __forceinline__ unsigned long long f2_pack(float lo, float hi) {
    unsigned long long r;
    asm("mov.b64 %0, {%1, %2};" : "=l"(r) : "f"(lo), "f"(hi));
    return r;
}
__device__ __forceinline__ void f2_unpack(unsigned long long v, float& lo, float& hi) {
    asm("mov.b64 {%0, %1}, %2;" : "=f"(lo), "=f"(hi) : "l"(v));
}
__device__ __forceinline__ unsigned long long f2_add(unsigned long long a, unsigned long long b) {
    unsigned long long r;
    asm("add.rn.f32x2 %0, %1, %2;" : "=l"(r) : "l"(a), "l"(b));
    return r;
}
__device__ __forceinline__ unsigned long long f2_mul(unsigned long long a, unsigned long long b) {
    unsigned long long r;
    asm("mul.rn.f32x2 %0, %1, %2;" : "=l"(r) : "l"(a), "l"(b));
    return r;
}

// ---------------- init ------------------------------------------------------
__global__ void init_kernel() {
    int t = blockIdx.x * blockDim.x + threadIdx.x;
    if (t == 0) g_ptot = 0;
    if (t < 384) {
        ((double*)g_sum)[t]   = 0.0;
        ((double*)g_sumsq)[t] = 0.0;
    }
}

// ---------------- farthest point sampling (bit-exact) -----------------------
// one block per batch, 256 threads, 16 points/thread (8 f32x2 pairs).
// Fewer warps => smaller barrier population + less issue backlog per SMSP.
__global__ __launch_bounds__(256, 1)
void fps_kernel(const float* __restrict__ xyz, float* __restrict__ newxyz) {
    int b = blockIdx.x, tid = threadIdx.x;
    const float* bx = xyz + (size_t)b * 3 * NN;

    unsigned long long px2[8], py2[8], pz2[8];
    float dist[16];
    {
        const float4* x4 = (const float4*)(bx);
        const float4* y4 = (const float4*)(bx + NN);
        const float4* z4 = (const float4*)(bx + 2 * NN);
#pragma unroll
        for (int h = 0; h < 4; h++) {
            float4 xa = x4[tid * 4 + h], ya = y4[tid * 4 + h], za = z4[tid * 4 + h];
            px2[2*h]   = f2_pack(xa.x, xa.y);
            px2[2*h+1] = f2_pack(xa.z, xa.w);
            py2[2*h]   = f2_pack(ya.x, ya.y);
            py2[2*h+1] = f2_pack(ya.z, ya.w);
            pz2[2*h]   = f2_pack(za.x, za.y);
            pz2[2*h+1] = f2_pack(za.z, za.w);
        }
    }
#pragma unroll
    for (int j = 0; j < 16; j++) dist[j] = 1e10f;

    __shared__ unsigned long long skey[2][8];   // {bits<<32 | widx} per warp
    __shared__ int fhist[SS];
    int lane = tid & 31, wid = tid >> 5;
    int farthest = 0;

    for (int it = 0; it < SS; ++it) {
        if (tid == 0) fhist[it] = farthest;
        float cx = __ldg(bx + farthest);
        float cy = __ldg(bx + NN + farthest);
        float cz = __ldg(bx + 2 * NN + farthest);
        unsigned long long ncx = f2_pack(-cx, -cx);
        unsigned long long ncy = f2_pack(-cy, -cy);
        unsigned long long ncz = f2_pack(-cz, -cz);

        // packed distance update: per lane rn(sub), rn(mul), rn((xx+yy)+zz)
#pragma unroll
        for (int k = 0; k < 8; k++) {
            unsigned long long dx = f2_add(px2[k], ncx);
            unsigned long long dy = f2_add(py2[k], ncy);
            unsigned long long dz = f2_add(pz2[k], ncz);
            unsigned long long s  = f2_add(f2_add(f2_mul(dx, dx), f2_mul(dy, dy)),
                                           f2_mul(dz, dz));
            float d0, d1;
            f2_unpack(s, d0, d1);
            dist[2*k]   = fminf(dist[2*k],   d0);
            dist[2*k+1] = fminf(dist[2*k+1], d1);
        }

        // local argmax tree over 16, first-index ties (strict > keeps lower)
        float v1[8]; int i1[8];
#pragma unroll
        for (int k = 0; k < 8; k++) {
            bool g = dist[2*k+1] > dist[2*k];
            v1[k] = g ? dist[2*k+1] : dist[2*k];
            i1[k] = g ? 2*k+1 : 2*k;
        }
        float v2[4]; int i2[4];
#pragma unroll
        for (int k = 0; k < 4; k++) {
            bool g = v1[2*k+1] > v1[2*k];
            v2[k] = g ? v1[2*k+1] : v1[2*k];
            i2[k] = g ? i1[2*k+1] : i1[2*k];
        }
        bool g0 = v2[1] > v2[0];
        float va = g0 ? v2[1] : v2[0]; int ia = g0 ? i2[1] : i2[0];
        bool g1 = v2[3] > v2[2];
        float vb = g1 ? v2[3] : v2[2]; int ib = g1 ? i2[3] : i2[2];
        bool g2 = vb > va;
        float bv = g2 ? vb : va;
        int bi = tid * 16 + (g2 ? ib : ia);

        // warp argmax via REDUX on float bits (dists >= 0 -> u32 monotone)
        unsigned bits = __float_as_uint(bv);
        unsigned wmax = __reduce_max_sync(0xffffffffu, bits);
        unsigned mm   = __ballot_sync(0xffffffffu, bits == wmax);
        int src  = __ffs(mm) - 1;                 // lowest lane = lowest index
        int widx = __shfl_sync(0xffffffffu, bi, src);

        int buf = it & 1;
        if (lane == 0)
            skey[buf][wid] = ((unsigned long long)wmax << 32) | (unsigned)widx;
        __syncthreads();

        // block argmax over 8 warp winners: lane loads entry (lane&7);
        // redux on high word; ballot+ffs -> lowest wid (first-index tiebreak).
        unsigned long long e = skey[buf][lane & 7];
        unsigned eb   = (unsigned)(e >> 32);
        int      ei   = (int)(unsigned)e;
        unsigned bmax = __reduce_max_sync(0xffffffffu, eb);
        unsigned wm   = __ballot_sync(0xffffffffu, eb == bmax);
        int fl = __ffs(wm) - 1;
        farthest = __shfl_sync(0xffffffffu, ei, fl);
    }

    // bulk centroid write-out
    __syncthreads();
    for (int i = tid; i < SS; i += 256) {
        int idx = fhist[i];
        newxyz[(size_t)b * 3 * SS + i]          = __ldg(bx + idx);
        newxyz[(size_t)b * 3 * SS + SS + i]     = __ldg(bx + NN + idx);
        newxyz[(size_t)b * 3 * SS + 2 * SS + i] = __ldg(bx + 2 * NN + idx);
    }
}

// ---------------- ball query + compaction + gather --------------------------
// one warp per group (b, s)
// Distance matches the reference's fp32 arithmetic op-for-op:
//   t  = fma-chain dot (GEMM-style, c order 0,1,2)
//   ns = ((cx*cx + cy*cy) + cz*cz)   plain mul/add (elementwise fusion, no FMA)
//   d  = ((-2*t) + ns) + nd          plain mul/add, this association order
__global__ __launch_bounds__(128)
void query_gather_kernel(const float* __restrict__ xyz,
                         const float* __restrict__ pts,
                         const float* __restrict__ newxyz) {
    int gwarp = (blockIdx.x * blockDim.x + threadIdx.x) >> 5;
    int lane  = threadIdx.x & 31;
    int wslot = (threadIdx.x >> 5) & 3;
    int b = gwarp >> 10, s = gwarp & (SS - 1);

    __shared__ int sgidx[4][KK];
    int* gidx = sgidx[wslot];

    const float* bx = xyz + (size_t)b * 3 * NN;
    float cx = newxyz[(size_t)b * 3 * SS + s];
    float cy = newxyz[(size_t)b * 3 * SS + SS + s];
    float cz = newxyz[(size_t)b * 3 * SS + 2 * SS + s];
    float ns = __fadd_rn(__fadd_rn(__fmul_rn(cx, cx), __fmul_rn(cy, cy)),
                         __fmul_rn(cz, cz));

    int cnt = 0;
    for (int j = 0; j < NN / 32; j++) {
        int i = j * 32 + lane;
        float dx = bx[i], dy = bx[NN + i], dz = bx[2 * NN + i];
        float nd = __fadd_rn(__fadd_rn(__fmul_rn(dx, dx), __fmul_rn(dy, dy)),
                             __fmul_rn(dz, dz));
        float t  = __fmaf_rn(cz, dz, __fmaf_rn(cy, dy, __fmul_rn(cx, dx)));
        float d  = __fadd_rn(__fadd_rn(__fmul_rn(-2.0f, t), ns), nd);
        bool ok = !(d > 0.04f);
        unsigned m = __ballot_sync(0xffffffffu, ok);
        int pos = cnt + __popc(m & ((1u << lane) - 1u));
        if (ok && pos < KK) gidx[pos] = i;
        cnt += __popc(m);
        if (cnt >= KK) break;
    }
    int mcnt = min(cnt, KK);
    __syncwarp();

    int base = 0;
    if (lane == 0) {
        base = atomicAdd(&g_ptot, mcnt);
        g_gstart[gwarp] = base;
        g_gcnt[gwarp]   = mcnt;
    }
    base = __shfl_sync(0xffffffffu, base, 0);

    if (lane < mcnt) {
        int i = gidx[lane];
        const float* bp = pts + (size_t)b * 3 * NN;
        float* dst = g_x0 + (size_t)(base + lane) * 8;
        dst[0] = __fsub_rn(bx[i], cx);
        dst[1] = __fsub_rn(bx[NN + i], cy);
        dst[2] = __fsub_rn(bx[2 * NN + i], cz);
        dst[3] = bp[i];
        dst[4] = bp[NN + i];
        dst[5] = bp[2 * NN + i];
        dst[6] = 0.0f;
        dst[7] = 0.0f;
        g_wt[base + lane] = (lane == 0) ? (float)(KK - mcnt + 1) : 1.0f;
    }
}

// ---------------- unified GEMM + fused output stats --------------------------
// CIN: input channels (8 padded, or 64). COUT: 64 or 128.
// LOUT: 0 -> x0->y1 (raw input), 1 -> y1->y2 (BN+ReLU in), 2 -> y2->y3.
// Epilogue: weighted per-channel sum/sumsq partials (float per thread),
// block-reduced via smem float atomics, one double atomicAdd per ch per block.
template<int CIN, int COUT, int LOUT>
__global__ __launch_bounds__(128)
void gemm_stats_kernel(const float* __restrict__ W) {
    constexpr bool BN_IN = (LOUT > 0);
    constexpr int TX = COUT / 8;     // 8 or 16
    constexpr int TY = 128 / TX;     // 16 or 8
    constexpr int PT = 64 / TY;      // 4 or 8 positions per thread

    __shared__ float Xs[64 * CIN];
    __shared__ float Ws[CIN * COUT];
    __shared__ float ssum[COUT], ssq[COUT];

    const float* Yin  = (LOUT == 0) ? g_x0 : (LOUT == 1 ? g_y1 : g_y2);
    float*       Yout = (LOUT == 0) ? g_y1 : (LOUT == 1 ? g_y2 : g_y3);
    const float* A  = g_A[BN_IN ? LOUT - 1 : 0];
    const float* Bc = g_Bc[BN_IN ? LOUT - 1 : 0];

    int tid = threadIdx.x;
    int tx = tid % TX, ty = tid / TX;

    for (int idx = tid; idx < CIN * COUT; idx += 128) {
        int c = idx % CIN, o = idx / CIN;
        float w;
        if (LOUT == 0) w = (c < 6) ? W[o * 6 + c] : 0.0f;   // W is (64, 6)
        else           w = W[o * 64 + c];                    // W is (COUT, 64)
        Ws[c * COUT + o] = w;
    }
    if (tid < COUT) { ssum[tid] = 0.0f; ssq[tid] = 0.0f; }
    __syncthreads();

    float ps[8], pq[8];
#pragma unroll
    for (int i = 0; i < 8; i++) { ps[i] = 0.0f; pq[i] = 0.0f; }

    int ptot = g_ptot;
    int ntiles = (ptot + 63) >> 6;
    for (int t = blockIdx.x; t < ntiles; t += gridDim.x) {
        int p0 = t * 64;
        for (int idx = tid; idx < 64 * CIN; idx += 128) {
            int c = idx % CIN, pl = idx / CIN;
            int p = p0 + pl;
            float v = 0.0f;
            if (p < ptot) {
                float y = Yin[(size_t)p * CIN + c];
                v = BN_IN ? fmaxf(fmaf(A[c], y, Bc[c]), 0.0f) : y;
            }
            Xs[pl * CIN + c] = v;
        }
        __syncthreads();

        float acc[PT][8];
#pragma unroll
        for (int j = 0; j < PT; j++)
#pragma unroll
            for (int i = 0; i < 8; i++) acc[j][i] = 0.0f;

#pragma unroll
        for (int c = 0; c < CIN; c++) {
            float wv[8], xv[PT];
#pragma unroll
            for (int i = 0; i < 8; i++) wv[i] = Ws[c * COUT + tx + i * TX];
#pragma unroll
            for (int j = 0; j < PT; j++) xv[j] = Xs[(ty * PT + j) * CIN + c];
#pragma unroll
            for (int j = 0; j < PT; j++)
#pragma unroll
                for (int i = 0; i < 8; i++)
                    acc[j][i] = fmaf(xv[j], wv[i], acc[j][i]);
        }

#pragma unroll
        for (int j = 0; j < PT; j++) {
            int p = p0 + ty * PT + j;
            if (p < ptot) {
                float w = g_wt[p];
#pragma unroll
                for (int i = 0; i < 8; i++) {
                    float v = acc[j][i];
                    Yout[(size_t)p * COUT + tx + i * TX] = v;
                    float wv = w * v;
                    ps[i] += wv;
                    pq[i] += wv * v;
                }
            }
        }
        __syncthreads();
    }

    // block-level stats reduction
#pragma unroll
    for (int i = 0; i < 8; i++) {
        atomicAdd(&ssum[tx + i * TX], ps[i]);
        atomicAdd(&ssq[tx + i * TX],  pq[i]);
    }
    __syncthreads();
    if (tid < COUT) {
        atomicAdd(&g_sum[LOUT][tid],   (double)ssum[tid]);
        atomicAdd(&g_sumsq[LOUT][tid], (double)ssq[tid]);
    }
}

// ---------------- finalize BN affine ----------------------------------------
__global__ void finalize_kernel(const float* __restrict__ gamma,
                                const float* __restrict__ beta,
                                int layer, int cout) {
    int o = threadIdx.x;
    if (o >= cout) return;
    double mean = g_sum[layer][o] / TOTAL_DIV;
    double var  = g_sumsq[layer][o] / TOTAL_DIV - mean * mean;
    double inv  = 1.0 / sqrt(var + 1e-5);
    double ga   = (double)gamma[o];
    g_A[layer][o]  = (float)(ga * inv);
    g_Bc[layer][o] = (float)((double)beta[o] - mean * ga * inv);
}

// ---------------- final BN+ReLU + max over group ----------------------------
__global__ __launch_bounds__(128)
void maxpool_kernel(float* __restrict__ feats) {
    int g = blockIdx.x;
    int o = threadIdx.x;               // 128
    int m  = g_gcnt[g];
    int st = g_gstart[g];
    float Aa = g_A[2][o], Bb = g_Bc[2][o];
    float mx = -3.4e38f;
    for (int k = 0; k < m; k++) {
        float y = g_y3[(size_t)(st + k) * 128 + o];
        float z = fmaxf(fmaf(Aa, y, Bb), 0.0f);
        mx = fmaxf(mx, z);
    }
    int b = g >> 10, s = g & (SS - 1);
    feats[((size_t)b * 128 + o) * SS + s] = mx;
}

// ---------------- launch ----------------------------------------------------
extern "C" void kernel_launch(void* const* d_in, const int* in_sizes, int n_in,
                              void* d_out, int out_size) {
    const float* xyz = (const float*)d_in[0];
    const float* pts = (const float*)d_in[1];
    const float* w0  = (const float*)d_in[2];
    const float* g0  = (const float*)d_in[4];
    const float* be0 = (const float*)d_in[5];
    const float* w1  = (const float*)d_in[6];
    const float* g1  = (const float*)d_in[8];
    const float* be1 = (const float*)d_in[9];
    const float* w2  = (const float*)d_in[10];
    const float* g2  = (const float*)d_in[12];
    const float* be2 = (const float*)d_in[13];

    float* out    = (float*)d_out;
    float* newxyz = out;                              // (B,3,S)
    float* feats  = out + (size_t)BB * 3 * SS;        // (B,128,S)

    init_kernel<<<2, 256>>>();
    fps_kernel<<<BB, 256>>>(xyz, newxyz);
    query_gather_kernel<<<GG / 4, 128>>>(xyz, pts, newxyz);

    gemm_stats_kernel<8, 64, 0><<<1024, 128>>>(w0);
    finalize_kernel<<<1, 128>>>(g0, be0, 0, 64);

    gemm_stats_kernel<64, 64, 1><<<1024, 128>>>(w1);
    finalize_kernel<<<1, 128>>>(g1, be1, 1, 64);

    gemm_stats_kernel<64, 128, 2><<<1024, 128>>>(w2);
    finalize_kernel<<<1, 128>>>(g2, be2, 2, 128);

    maxpool_kernel<<<GG, 128>>>(feats);
}

// round 13
// speedup vs baseline: 3.9264x; 1.0206x over previous
#include <cuda_runtime.h>
#include <cuda_bf16.h>
#include <math.h>

#define BB 16
#define NN 4096
#define SS 1024
#define KK 32
#define GG (BB*SS)            // 16384 groups
#define MAXP (GG*KK)          // 524288 worst-case positions
#define TOTAL_DIV 524288.0    // BN divisor: B*K*S (= 2^19, exact fp scaling)

// ---------------- scratch (static device globals; no runtime allocation) ----
__device__ float  g_x0[(size_t)MAXP * 8];     // compacted input features (padded to 8 ch)
__device__ float  g_wt[MAXP];                  // multiplicity weight per position
__device__ int    g_gstart[GG];
__device__ int    g_gcnt[GG];
__device__ int    g_ptot;
__device__ float  g_y1[(size_t)MAXP * 64];
__device__ float  g_y2[(size_t)MAXP * 64];
__device__ float  g_y3[(size_t)MAXP * 128];
__device__ double g_sum[3][128];
__device__ double g_sumsq[3][128];
__device__ float  g_A[3][128];
__device__ float  g_Bc[3][128];

// ---------------- packed f32x2 helpers (per-lane .rn semantics == scalar) ---
__device__ __forceinline__ unsigned long long f2_pack(float lo, float hi) {
    unsigned long long r;
    asm("mov.b64 %0, {%1, %2};" : "=l"(r) : "f"(lo), "f"(hi));
    return r;
}
__device__ __forceinline__ void f2_unpack(unsigned long long v, float& lo, float& hi) {
    asm("mov.b64 {%0, %1}, %2;" : "=f"(lo), "=f"(hi) : "l"(v));
}
__device__ __forceinline__ unsigned long long f2_add(unsigned long long a, unsigned long long b) {
    unsigned long long r;
    asm("add.rn.f32x2 %0, %1, %2;" : "=l"(r) : "l"(a), "l"(b));
    return r;
}
__device__ __forceinline__ unsigned long long f2_mul(unsigned long long a, unsigned long long b) {
    unsigned long long r;
    asm("mul.rn.f32x2 %0, %1, %2;" : "=l"(r) : "l"(a), "l"(b));
    return r;
}

// ---------------- farthest point sampling (bit-exact) -----------------------
// one block per batch, 256 threads, 16 points/thread (8 f32x2 pairs).
// Block 0 additionally zeroes the global accumulators (init merged here;
// all consumers run in later kernels, so stream order guarantees visibility).
__global__ __launch_bounds__(256, 1)
void fps_kernel(const float* __restrict__ xyz, float* __restrict__ newxyz) {
    int b = blockIdx.x, tid = threadIdx.x;
    const float* bx = xyz + (size_t)b * 3 * NN;

    if (b == 0) {
        if (tid == 0) g_ptot = 0;
        for (int t = tid; t < 384; t += 256) {
            ((double*)g_sum)[t]   = 0.0;
            ((double*)g_sumsq)[t] = 0.0;
        }
    }

    unsigned long long px2[8], py2[8], pz2[8];
    float dist[16];
    {
        const float4* x4 = (const float4*)(bx);
        const float4* y4 = (const float4*)(bx + NN);
        const float4* z4 = (const float4*)(bx + 2 * NN);
#pragma unroll
        for (int h = 0; h < 4; h++) {
            float4 xa = x4[tid * 4 + h], ya = y4[tid * 4 + h], za = z4[tid * 4 + h];
            px2[2*h]   = f2_pack(xa.x, xa.y);
            px2[2*h+1] = f2_pack(xa.z, xa.w);
            py2[2*h]   = f2_pack(ya.x, ya.y);
            py2[2*h+1] = f2_pack(ya.z, ya.w);
            pz2[2*h]   = f2_pack(za.x, za.y);
            pz2[2*h+1] = f2_pack(za.z, za.w);
        }
    }
#pragma unroll
    for (int j = 0; j < 16; j++) dist[j] = 1e10f;

    __shared__ unsigned long long skey[2][8];   // {bits<<32 | widx} per warp
    __shared__ int fhist[SS];
    int lane = tid & 31, wid = tid >> 5;
    int farthest = 0;

    for (int it = 0; it < SS; ++it) {
        if (tid == 0) fhist[it] = farthest;
        float cx = __ldg(bx + farthest);
        float cy = __ldg(bx + NN + farthest);
        float cz = __ldg(bx + 2 * NN + farthest);
        unsigned long long ncx = f2_pack(-cx, -cx);
        unsigned long long ncy = f2_pack(-cy, -cy);
        unsigned long long ncz = f2_pack(-cz, -cz);

        // packed distance update: per lane rn(sub), rn(mul), rn((xx+yy)+zz)
#pragma unroll
        for (int k = 0; k < 8; k++) {
            unsigned long long dx = f2_add(px2[k], ncx);
            unsigned long long dy = f2_add(py2[k], ncy);
            unsigned long long dz = f2_add(pz2[k], ncz);
            unsigned long long s  = f2_add(f2_add(f2_mul(dx, dx), f2_mul(dy, dy)),
                                           f2_mul(dz, dz));
            float d0, d1;
            f2_unpack(s, d0, d1);
            dist[2*k]   = fminf(dist[2*k],   d0);
            dist[2*k+1] = fminf(dist[2*k+1], d1);
        }

        // local argmax tree over 16, first-index ties (strict > keeps lower)
        float v1[8]; int i1[8];
#pragma unroll
        for (int k = 0; k < 8; k++) {
            bool g = dist[2*k+1] > dist[2*k];
            v1[k] = g ? dist[2*k+1] : dist[2*k];
            i1[k] = g ? 2*k+1 : 2*k;
        }
        float v2[4]; int i2[4];
#pragma unroll
        for (int k = 0; k < 4; k++) {
            bool g = v1[2*k+1] > v1[2*k];
            v2[k] = g ? v1[2*k+1] : v1[2*k];
            i2[k] = g ? i1[2*k+1] : i1[2*k];
        }
        bool g0 = v2[1] > v2[0];
        float va = g0 ? v2[1] : v2[0]; int ia = g0 ? i2[1] : i2[0];
        bool g1 = v2[3] > v2[2];
        float vb = g1 ? v2[3] : v2[2]; int ib = g1 ? i2[3] : i2[2];
        bool g2 = vb > va;
        float bv = g2 ? vb : va;
        int bi = tid * 16 + (g2 ? ib : ia);

        // warp argmax via REDUX on float bits (dists >= 0 -> u32 monotone)
        unsigned bits = __float_as_uint(bv);
        unsigned wmax = __reduce_max_sync(0xffffffffu, bits);
        unsigned mm   = __ballot_sync(0xffffffffu, bits == wmax);
        int src  = __ffs(mm) - 1;                 // lowest lane = lowest index
        int widx = __shfl_sync(0xffffffffu, bi, src);

        int buf = it & 1;
        if (lane == 0)
            skey[buf][wid] = ((unsigned long long)wmax << 32) | (unsigned)widx;
        __syncthreads();

        // block argmax over 8 warp winners: lane loads entry (lane&7);
        // redux on high word; ballot+ffs -> lowest wid (first-index tiebreak).
        unsigned long long e = skey[buf][lane & 7];
        unsigned eb   = (unsigned)(e >> 32);
        int      ei   = (int)(unsigned)e;
        unsigned bmax = __reduce_max_sync(0xffffffffu, eb);
        unsigned wm   = __ballot_sync(0xffffffffu, eb == bmax);
        int fl = __ffs(wm) - 1;
        farthest = __shfl_sync(0xffffffffu, ei, fl);
    }

    // bulk centroid write-out
    __syncthreads();
    for (int i = tid; i < SS; i += 256) {
        int idx = fhist[i];
        newxyz[(size_t)b * 3 * SS + i]          = __ldg(bx + idx);
        newxyz[(size_t)b * 3 * SS + SS + i]     = __ldg(bx + NN + idx);
        newxyz[(size_t)b * 3 * SS + 2 * SS + i] = __ldg(bx + 2 * NN + idx);
    }
}

// ---------------- ball query + compaction + gather --------------------------
// one warp per group (b, s); TWO points per lane via float2 loads (halves the
// LDG issue count, which is this kernel's binding floor).
// Distance matches the reference's fp32 arithmetic op-for-op:
//   t  = fma-chain dot (GEMM-style, c order 0,1,2)
//   ns = ((cx*cx + cy*cy) + cz*cz)   plain mul/add (elementwise fusion, no FMA)
//   d  = ((-2*t) + ns) + nd          plain mul/add, this association order
// Compaction order: lane l covers indices {64j+2l, 64j+2l+1}; two ballots give
// an index-ordered prefix count, identical selection to the 1-pt/lane version.
__global__ __launch_bounds__(128)
void query_gather_kernel(const float* __restrict__ xyz,
                         const float* __restrict__ pts,
                         const float* __restrict__ newxyz) {
    int gwarp = (blockIdx.x * blockDim.x + threadIdx.x) >> 5;
    int lane  = threadIdx.x & 31;
    int wslot = (threadIdx.x >> 5) & 3;
    int b = gwarp >> 10, s = gwarp & (SS - 1);

    __shared__ int sgidx[4][KK];
    int* gidx = sgidx[wslot];

    const float* bx = xyz + (size_t)b * 3 * NN;
    float cx = newxyz[(size_t)b * 3 * SS + s];
    float cy = newxyz[(size_t)b * 3 * SS + SS + s];
    float cz = newxyz[(size_t)b * 3 * SS + 2 * SS + s];
    float ns = __fadd_rn(__fadd_rn(__fmul_rn(cx, cx), __fmul_rn(cy, cy)),
                         __fmul_rn(cz, cz));

    unsigned below = (1u << lane) - 1u;
    int cnt = 0;
    for (int j = 0; j < NN / 64; j++) {
        int i0 = j * 64 + 2 * lane;
        float2 X = *(const float2*)(bx + i0);
        float2 Y = *(const float2*)(bx + NN + i0);
        float2 Z = *(const float2*)(bx + 2 * NN + i0);

        float nda = __fadd_rn(__fadd_rn(__fmul_rn(X.x, X.x), __fmul_rn(Y.x, Y.x)),
                              __fmul_rn(Z.x, Z.x));
        float ta  = __fmaf_rn(cz, Z.x, __fmaf_rn(cy, Y.x, __fmul_rn(cx, X.x)));
        float da  = __fadd_rn(__fadd_rn(__fmul_rn(-2.0f, ta), ns), nda);

        float ndb = __fadd_rn(__fadd_rn(__fmul_rn(X.y, X.y), __fmul_rn(Y.y, Y.y)),
                              __fmul_rn(Z.y, Z.y));
        float tb  = __fmaf_rn(cz, Z.y, __fmaf_rn(cy, Y.y, __fmul_rn(cx, X.y)));
        float db  = __fadd_rn(__fadd_rn(__fmul_rn(-2.0f, tb), ns), ndb);

        bool ok0 = !(da > 0.04f);
        bool ok1 = !(db > 0.04f);
        unsigned m0 = __ballot_sync(0xffffffffu, ok0);
        unsigned m1 = __ballot_sync(0xffffffffu, ok1);
        int pos0 = cnt + __popc(m0 & below) + __popc(m1 & below);
        int pos1 = pos0 + (ok0 ? 1 : 0);
        if (ok0 && pos0 < KK) gidx[pos0] = i0;
        if (ok1 && pos1 < KK) gidx[pos1] = i0 + 1;
        cnt += __popc(m0) + __popc(m1);
        if (cnt >= KK) break;
    }
    int mcnt = min(cnt, KK);
    __syncwarp();

    int base = 0;
    if (lane == 0) {
        base = atomicAdd(&g_ptot, mcnt);
        g_gstart[gwarp] = base;
        g_gcnt[gwarp]   = mcnt;
    }
    base = __shfl_sync(0xffffffffu, base, 0);

    if (lane < mcnt) {
        int i = gidx[lane];
        const float* bp = pts + (size_t)b * 3 * NN;
        float* dst = g_x0 + (size_t)(base + lane) * 8;
        dst[0] = __fsub_rn(bx[i], cx);
        dst[1] = __fsub_rn(bx[NN + i], cy);
        dst[2] = __fsub_rn(bx[2 * NN + i], cz);
        dst[3] = bp[i];
        dst[4] = bp[NN + i];
        dst[5] = bp[2 * NN + i];
        dst[6] = 0.0f;
        dst[7] = 0.0f;
        g_wt[base + lane] = (lane == 0) ? (float)(KK - mcnt + 1) : 1.0f;
    }
}

// ---------------- unified GEMM + fused input-affine + output stats -----------
// CIN: input channels (8 padded, or 64). COUT: 64 or 128.
// LOUT: 0 -> x0->y1 (raw input), 1 -> y1->y2 (BN+ReLU in), 2 -> y2->y3.
// For LOUT>=1 the BN affine of layer LOUT-1 is computed PER BLOCK from the
// completed g_sum/g_sumsq (deterministic, identical across blocks) — the
// separate finalize launch is eliminated. Mean scaling by 1/2^19 is exact.
// Epilogue: weighted per-channel sum/sumsq partials (float per thread),
// block-reduced via smem float atomics, one double atomicAdd per ch per block.
template<int CIN, int COUT, int LOUT>
__global__ __launch_bounds__(128)
void gemm_stats_kernel(const float* __restrict__ W,
                       const float* __restrict__ gamma,
                       const float* __restrict__ beta) {
    constexpr bool BN_IN = (LOUT > 0);
    constexpr int TX = COUT / 8;     // 8 or 16
    constexpr int TY = 128 / TX;     // 16 or 8
    constexpr int PT = 64 / TY;      // 4 or 8 positions per thread

    __shared__ float Xs[64 * CIN];
    __shared__ float Ws[CIN * COUT];
    __shared__ float ssum[COUT], ssq[COUT];
    __shared__ float sA[64], sBc[64];

    const float* Yin  = (LOUT == 0) ? g_x0 : (LOUT == 1 ? g_y1 : g_y2);
    float*       Yout = (LOUT == 0) ? g_y1 : (LOUT == 1 ? g_y2 : g_y3);

    int tid = threadIdx.x;
    int tx = tid % TX, ty = tid / TX;

    for (int idx = tid; idx < CIN * COUT; idx += 128) {
        int c = idx % CIN, o = idx / CIN;
        float w;
        if (LOUT == 0) w = (c < 6) ? W[o * 6 + c] : 0.0f;   // W is (64, 6)
        else           w = W[o * 64 + c];                    // W is (COUT, 64)
        Ws[c * COUT + o] = w;
    }
    if (tid < COUT) { ssum[tid] = 0.0f; ssq[tid] = 0.0f; }
    if (BN_IN && tid < 64) {
        double dmean = g_sum[LOUT - 1][tid] * (1.0 / TOTAL_DIV);   // exact /2^19
        double dvar  = g_sumsq[LOUT - 1][tid] * (1.0 / TOTAL_DIV) - dmean * dmean;
        float inv = 1.0f / sqrtf((float)dvar + 1e-5f);
        float Aa  = gamma[tid] * inv;
        sA[tid]  = Aa;
        sBc[tid] = beta[tid] - (float)dmean * Aa;
    }
    __syncthreads();

    float ps[8], pq[8];
#pragma unroll
    for (int i = 0; i < 8; i++) { ps[i] = 0.0f; pq[i] = 0.0f; }

    int ptot = g_ptot;
    int ntiles = (ptot + 63) >> 6;
    for (int t = blockIdx.x; t < ntiles; t += gridDim.x) {
        int p0 = t * 64;
        for (int idx = tid; idx < 64 * CIN; idx += 128) {
            int c = idx % CIN, pl = idx / CIN;
            int p = p0 + pl;
            float v = 0.0f;
            if (p < ptot) {
                float y = Yin[(size_t)p * CIN + c];
                v = BN_IN ? fmaxf(fmaf(sA[c], y, sBc[c]), 0.0f) : y;
            }
            Xs[pl * CIN + c] = v;
        }
        __syncthreads();

        float acc[PT][8];
#pragma unroll
        for (int j = 0; j < PT; j++)
#pragma unroll
            for (int i = 0; i < 8; i++) acc[j][i] = 0.0f;

#pragma unroll
        for (int c = 0; c < CIN; c++) {
            float wv[8], xv[PT];
#pragma unroll
            for (int i = 0; i < 8; i++) wv[i] = Ws[c * COUT + tx + i * TX];
#pragma unroll
            for (int j = 0; j < PT; j++) xv[j] = Xs[(ty * PT + j) * CIN + c];
#pragma unroll
            for (int j = 0; j < PT; j++)
#pragma unroll
                for (int i = 0; i < 8; i++)
                    acc[j][i] = fmaf(xv[j], wv[i], acc[j][i]);
        }

#pragma unroll
        for (int j = 0; j < PT; j++) {
            int p = p0 + ty * PT + j;
            if (p < ptot) {
                float w = g_wt[p];
#pragma unroll
                for (int i = 0; i < 8; i++) {
                    float v = acc[j][i];
                    Yout[(size_t)p * COUT + tx + i * TX] = v;
                    float wv = w * v;
                    ps[i] += wv;
                    pq[i] += wv * v;
                }
            }
        }
        __syncthreads();
    }

    // block-level stats reduction
#pragma unroll
    for (int i = 0; i < 8; i++) {
        atomicAdd(&ssum[tx + i * TX], ps[i]);
        atomicAdd(&ssq[tx + i * TX],  pq[i]);
    }
    __syncthreads();
    if (tid < COUT) {
        atomicAdd(&g_sum[LOUT][tid],   (double)ssum[tid]);
        atomicAdd(&g_sumsq[LOUT][tid], (double)ssq[tid]);
    }
}

// ---------------- finalize BN affine (layer 2 only; feeds maxpool) ----------
__global__ void finalize_kernel(const float* __restrict__ gamma,
                                const float* __restrict__ beta,
                                int layer, int cout) {
    int o = threadIdx.x;
    if (o >= cout) return;
    double mean = g_sum[layer][o] / TOTAL_DIV;
    double var  = g_sumsq[layer][o] / TOTAL_DIV - mean * mean;
    double inv  = 1.0 / sqrt(var + 1e-5);
    double ga   = (double)gamma[o];
    g_A[layer][o]  = (float)(ga * inv);
    g_Bc[layer][o] = (float)((double)beta[o] - mean * ga * inv);
}

// ---------------- final BN+ReLU + max over group ----------------------------
__global__ __launch_bounds__(128)
void maxpool_kernel(float* __restrict__ feats) {
    int g = blockIdx.x;
    int o = threadIdx.x;               // 128
    int m  = g_gcnt[g];
    int st = g_gstart[g];
    float Aa = g_A[2][o], Bb = g_Bc[2][o];
    float mx = -3.4e38f;
    for (int k = 0; k < m; k++) {
        float y = g_y3[(size_t)(st + k) * 128 + o];
        float z = fmaxf(fmaf(Aa, y, Bb), 0.0f);
        mx = fmaxf(mx, z);
    }
    int b = g >> 10, s = g & (SS - 1);
    feats[((size_t)b * 128 + o) * SS + s] = mx;
}

// ---------------- launch ----------------------------------------------------
extern "C" void kernel_launch(void* const* d_in, const int* in_sizes, int n_in,
                              void* d_out, int out_size) {
    const float* xyz = (const float*)d_in[0];
    const float* pts = (const float*)d_in[1];
    const float* w0  = (const float*)d_in[2];
    const float* g0  = (const float*)d_in[4];
    const float* be0 = (const float*)d_in[5];
    const float* w1  = (const float*)d_in[6];
    const float* g1  = (const float*)d_in[8];
    const float* be1 = (const float*)d_in[9];
    const float* w2  = (const float*)d_in[10];
    const float* g2  = (const float*)d_in[12];
    const float* be2 = (const float*)d_in[13];

    float* out    = (float*)d_out;
    float* newxyz = out;                              // (B,3,S)
    float* feats  = out + (size_t)BB * 3 * SS;        // (B,128,S)

    fps_kernel<<<BB, 256>>>(xyz, newxyz);             // also zeroes accumulators
    query_gather_kernel<<<GG / 4, 128>>>(xyz, pts, newxyz);

    gemm_stats_kernel<8, 64, 0><<<1024, 128>>>(w0, g0, be0);
    gemm_stats_kernel<64, 64, 1><<<1024, 128>>>(w1, g0, be0);   // affine of layer 0
    gemm_stats_kernel<64, 128, 2><<<1024, 128>>>(w2, g1, be1);  // affine of layer 1

    finalize_kernel<<<1, 128>>>(g2, be2, 2, 128);
    maxpool_kernel<<<GG, 128>>>(feats);
}

// round 14
// speedup vs baseline: 4.0125x; 1.0219x over previous
#include <cuda_runtime.h>
#include <cuda_bf16.h>
#include <math.h>

#define BB 16
#define NN 4096
#define SS 1024
#define KK 32
#define GG (BB*SS)            // 16384 groups
#define MAXP (GG*KK)          // 524288 worst-case positions
#define TOTAL_DIV 524288.0    // BN divisor: B*K*S (= 2^19, exact fp scaling)

// ---------------- scratch (static device globals; no runtime allocation) ----
__device__ float  g_x0[(size_t)MAXP * 8];     // compacted input features (padded to 8 ch)
__device__ float  g_wt[MAXP];                  // multiplicity weight per position
__device__ int    g_gstart[GG];
__device__ int    g_gcnt[GG];
__device__ int    g_ptot;
__device__ float  g_y1[(size_t)MAXP * 64];
__device__ float  g_y2[(size_t)MAXP * 64];
__device__ float  g_y3[(size_t)MAXP * 128];
__device__ double g_sum[3][128];
__device__ double g_sumsq[3][128];
__device__ float  g_A[3][128];
__device__ float  g_Bc[3][128];

// ---------------- packed f32x2 helpers (per-lane .rn semantics == scalar) ---
__device__ __forceinline__ unsigned long long f2_pack(float lo, float hi) {
    unsigned long long r;
    asm("mov.b64 %0, {%1, %2};" : "=l"(r) : "f"(lo), "f"(hi));
    return r;
}
__device__ __forceinline__ void f2_unpack(unsigned long long v, float& lo, float& hi) {
    asm("mov.b64 {%0, %1}, %2;" : "=f"(lo), "=f"(hi) : "l"(v));
}
__device__ __forceinline__ unsigned long long f2_add(unsigned long long a, unsigned long long b) {
    unsigned long long r;
    asm("add.rn.f32x2 %0, %1, %2;" : "=l"(r) : "l"(a), "l"(b));
    return r;
}
__device__ __forceinline__ unsigned long long f2_mul(unsigned long long a, unsigned long long b) {
    unsigned long long r;
    asm("mul.rn.f32x2 %0, %1, %2;" : "=l"(r) : "l"(a), "l"(b));
    return r;
}

// ---------------- farthest point sampling (bit-exact) -----------------------
// one block per batch, 256 threads, 16 points/thread (8 f32x2 pairs).
// Block 0 additionally zeroes the global accumulators.
__global__ __launch_bounds__(256, 1)
void fps_kernel(const float* __restrict__ xyz, float* __restrict__ newxyz) {
    int b = blockIdx.x, tid = threadIdx.x;
    const float* bx = xyz + (size_t)b * 3 * NN;

    if (b == 0) {
        if (tid == 0) g_ptot = 0;
        for (int t = tid; t < 384; t += 256) {
            ((double*)g_sum)[t]   = 0.0;
            ((double*)g_sumsq)[t] = 0.0;
        }
    }

    unsigned long long px2[8], py2[8], pz2[8];
    float dist[16];
    {
        const float4* x4 = (const float4*)(bx);
        const float4* y4 = (const float4*)(bx + NN);
        const float4* z4 = (const float4*)(bx + 2 * NN);
#pragma unroll
        for (int h = 0; h < 4; h++) {
            float4 xa = x4[tid * 4 + h], ya = y4[tid * 4 + h], za = z4[tid * 4 + h];
            px2[2*h]   = f2_pack(xa.x, xa.y);
            px2[2*h+1] = f2_pack(xa.z, xa.w);
            py2[2*h]   = f2_pack(ya.x, ya.y);
            py2[2*h+1] = f2_pack(ya.z, ya.w);
            pz2[2*h]   = f2_pack(za.x, za.y);
            pz2[2*h+1] = f2_pack(za.z, za.w);
        }
    }
#pragma unroll
    for (int j = 0; j < 16; j++) dist[j] = 1e10f;

    __shared__ unsigned long long skey[2][8];   // {bits<<32 | widx} per warp
    __shared__ int fhist[SS];
    int lane = tid & 31, wid = tid >> 5;
    int farthest = 0;

    for (int it = 0; it < SS; ++it) {
        if (tid == 0) fhist[it] = farthest;
        float cx = __ldg(bx + farthest);
        float cy = __ldg(bx + NN + farthest);
        float cz = __ldg(bx + 2 * NN + farthest);
        unsigned long long ncx = f2_pack(-cx, -cx);
        unsigned long long ncy = f2_pack(-cy, -cy);
        unsigned long long ncz = f2_pack(-cz, -cz);

        // packed distance update: per lane rn(sub), rn(mul), rn((xx+yy)+zz)
#pragma unroll
        for (int k = 0; k < 8; k++) {
            unsigned long long dx = f2_add(px2[k], ncx);
            unsigned long long dy = f2_add(py2[k], ncy);
            unsigned long long dz = f2_add(pz2[k], ncz);
            unsigned long long s  = f2_add(f2_add(f2_mul(dx, dx), f2_mul(dy, dy)),
                                           f2_mul(dz, dz));
            float d0, d1;
            f2_unpack(s, d0, d1);
            dist[2*k]   = fminf(dist[2*k],   d0);
            dist[2*k+1] = fminf(dist[2*k+1], d1);
        }

        // local argmax tree over 16, first-index ties (strict > keeps lower)
        float v1[8]; int i1[8];
#pragma unroll
        for (int k = 0; k < 8; k++) {
            bool g = dist[2*k+1] > dist[2*k];
            v1[k] = g ? dist[2*k+1] : dist[2*k];
            i1[k] = g ? 2*k+1 : 2*k;
        }
        float v2[4]; int i2[4];
#pragma unroll
        for (int k = 0; k < 4; k++) {
            bool g = v1[2*k+1] > v1[2*k];
            v2[k] = g ? v1[2*k+1] : v1[2*k];
            i2[k] = g ? i1[2*k+1] : i1[2*k];
        }
        bool g0 = v2[1] > v2[0];
        float va = g0 ? v2[1] : v2[0]; int ia = g0 ? i2[1] : i2[0];
        bool g1 = v2[3] > v2[2];
        float vb = g1 ? v2[3] : v2[2]; int ib = g1 ? i2[3] : i2[2];
        bool g2 = vb > va;
        float bv = g2 ? vb : va;
        int bi = tid * 16 + (g2 ? ib : ia);

        // warp argmax via REDUX on float bits (dists >= 0 -> u32 monotone)
        unsigned bits = __float_as_uint(bv);
        unsigned wmax = __reduce_max_sync(0xffffffffu, bits);
        unsigned mm   = __ballot_sync(0xffffffffu, bits == wmax);
        int src  = __ffs(mm) - 1;                 // lowest lane = lowest index
        int widx = __shfl_sync(0xffffffffu, bi, src);

        int buf = it & 1;
        if (lane == 0)
            skey[buf][wid] = ((unsigned long long)wmax << 32) | (unsigned)widx;
        __syncthreads();

        // block argmax over 8 warp winners (lowest-wid first-index tiebreak)
        unsigned long long e = skey[buf][lane & 7];
        unsigned eb   = (unsigned)(e >> 32);
        int      ei   = (int)(unsigned)e;
        unsigned bmax = __reduce_max_sync(0xffffffffu, eb);
        unsigned wm   = __ballot_sync(0xffffffffu, eb == bmax);
        int fl = __ffs(wm) - 1;
        farthest = __shfl_sync(0xffffffffu, ei, fl);
    }

    // bulk centroid write-out
    __syncthreads();
    for (int i = tid; i < SS; i += 256) {
        int idx = fhist[i];
        newxyz[(size_t)b * 3 * SS + i]          = __ldg(bx + idx);
        newxyz[(size_t)b * 3 * SS + SS + i]     = __ldg(bx + NN + idx);
        newxyz[(size_t)b * 3 * SS + 2 * SS + i] = __ldg(bx + 2 * NN + idx);
    }
}

// ---------------- ball query + compaction + gather --------------------------
// one warp per group (b, s); two points per lane via float2 loads.
// Distance matches the reference's fp32 arithmetic op-for-op.
__global__ __launch_bounds__(128)
void query_gather_kernel(const float* __restrict__ xyz,
                         const float* __restrict__ pts,
                         const float* __restrict__ newxyz) {
    int gwarp = (blockIdx.x * blockDim.x + threadIdx.x) >> 5;
    int lane  = threadIdx.x & 31;
    int wslot = (threadIdx.x >> 5) & 3;
    int b = gwarp >> 10, s = gwarp & (SS - 1);

    __shared__ int sgidx[4][KK];
    int* gidx = sgidx[wslot];

    const float* bx = xyz + (size_t)b * 3 * NN;
    float cx = newxyz[(size_t)b * 3 * SS + s];
    float cy = newxyz[(size_t)b * 3 * SS + SS + s];
    float cz = newxyz[(size_t)b * 3 * SS + 2 * SS + s];
    float ns = __fadd_rn(__fadd_rn(__fmul_rn(cx, cx), __fmul_rn(cy, cy)),
                         __fmul_rn(cz, cz));

    unsigned below = (1u << lane) - 1u;
    int cnt = 0;
    for (int j = 0; j < NN / 64; j++) {
        int i0 = j * 64 + 2 * lane;
        float2 X = *(const float2*)(bx + i0);
        float2 Y = *(const float2*)(bx + NN + i0);
        float2 Z = *(const float2*)(bx + 2 * NN + i0);

        float nda = __fadd_rn(__fadd_rn(__fmul_rn(X.x, X.x), __fmul_rn(Y.x, Y.x)),
                              __fmul_rn(Z.x, Z.x));
        float ta  = __fmaf_rn(cz, Z.x, __fmaf_rn(cy, Y.x, __fmul_rn(cx, X.x)));
        float da  = __fadd_rn(__fadd_rn(__fmul_rn(-2.0f, ta), ns), nda);

        float ndb = __fadd_rn(__fadd_rn(__fmul_rn(X.y, X.y), __fmul_rn(Y.y, Y.y)),
                              __fmul_rn(Z.y, Z.y));
        float tb  = __fmaf_rn(cz, Z.y, __fmaf_rn(cy, Y.y, __fmul_rn(cx, X.y)));
        float db  = __fadd_rn(__fadd_rn(__fmul_rn(-2.0f, tb), ns), ndb);

        bool ok0 = !(da > 0.04f);
        bool ok1 = !(db > 0.04f);
        unsigned m0 = __ballot_sync(0xffffffffu, ok0);
        unsigned m1 = __ballot_sync(0xffffffffu, ok1);
        int pos0 = cnt + __popc(m0 & below) + __popc(m1 & below);
        int pos1 = pos0 + (ok0 ? 1 : 0);
        if (ok0 && pos0 < KK) gidx[pos0] = i0;
        if (ok1 && pos1 < KK) gidx[pos1] = i0 + 1;
        cnt += __popc(m0) + __popc(m1);
        if (cnt >= KK) break;
    }
    int mcnt = min(cnt, KK);
    __syncwarp();

    int base = 0;
    if (lane == 0) {
        base = atomicAdd(&g_ptot, mcnt);
        g_gstart[gwarp] = base;
        g_gcnt[gwarp]   = mcnt;
    }
    base = __shfl_sync(0xffffffffu, base, 0);

    if (lane < mcnt) {
        int i = gidx[lane];
        const float* bp = pts + (size_t)b * 3 * NN;
        float* dst = g_x0 + (size_t)(base + lane) * 8;
        dst[0] = __fsub_rn(bx[i], cx);
        dst[1] = __fsub_rn(bx[NN + i], cy);
        dst[2] = __fsub_rn(bx[2 * NN + i], cz);
        dst[3] = bp[i];
        dst[4] = bp[NN + i];
        dst[5] = bp[2 * NN + i];
        dst[6] = 0.0f;
        dst[7] = 0.0f;
        g_wt[base + lane] = (lane == 0) ? (float)(KK - mcnt + 1) : 1.0f;
    }
}

// ---------------- unified GEMM + fused input-affine + output stats -----------
// Vectorized streams: thread owns channels [tx*4, tx*4+4) and
// [COUT/2 + tx*4, +4) -> weights 2x LDS.128/c, outputs 2x STG.128/pos.
// Tile fill via float4 global loads + float4 smem stores (BN in registers).
// FFMA chain over ascending c unchanged -> GEMM results bit-identical.
template<int CIN, int COUT, int LOUT>
__global__ __launch_bounds__(128)
void gemm_stats_kernel(const float* __restrict__ W,
                       const float* __restrict__ gamma,
                       const float* __restrict__ beta) {
    constexpr bool BN_IN = (LOUT > 0);
    constexpr int TX = COUT / 8;     // 8 or 16
    constexpr int TY = 128 / TX;     // 16 or 8
    constexpr int PT = 64 / TY;      // 4 or 8 positions per thread
    constexpr int HALF = COUT / 2;

    __shared__ float Xs[64 * CIN];       // [pos][c], contiguous in c
    __shared__ float Ws[CIN * COUT];     // [c][o]
    __shared__ float ssum[COUT], ssq[COUT];
    __shared__ float sA[64], sBc[64];

    const float* Yin  = (LOUT == 0) ? g_x0 : (LOUT == 1 ? g_y1 : g_y2);
    float*       Yout = (LOUT == 0) ? g_y1 : (LOUT == 1 ? g_y2 : g_y3);

    int tid = threadIdx.x;
    int tx = tid % TX, ty = tid / TX;

    for (int idx = tid; idx < CIN * COUT; idx += 128) {
        int c = idx % CIN, o = idx / CIN;
        float w;
        if (LOUT == 0) w = (c < 6) ? W[o * 6 + c] : 0.0f;   // W is (64, 6)
        else           w = W[o * 64 + c];                    // W is (COUT, 64)
        Ws[c * COUT + o] = w;
    }
    if (tid < COUT) { ssum[tid] = 0.0f; ssq[tid] = 0.0f; }
    if (BN_IN && tid < 64) {
        double dmean = g_sum[LOUT - 1][tid] * (1.0 / TOTAL_DIV);   // exact /2^19
        double dvar  = g_sumsq[LOUT - 1][tid] * (1.0 / TOTAL_DIV) - dmean * dmean;
        float inv = 1.0f / sqrtf((float)dvar + 1e-5f);
        float Aa  = gamma[tid] * inv;
        sA[tid]  = Aa;
        sBc[tid] = beta[tid] - (float)dmean * Aa;
    }
    __syncthreads();

    float ps[8], pq[8];
#pragma unroll
    for (int i = 0; i < 8; i++) { ps[i] = 0.0f; pq[i] = 0.0f; }

    int ptot = g_ptot;
    int ntiles = (ptot + 63) >> 6;
    for (int t = blockIdx.x; t < ntiles; t += gridDim.x) {
        int p0 = t * 64;
        // float4 tile fill: 64*CIN/4 quads
#pragma unroll 2
        for (int q = tid; q < 64 * CIN / 4; q += 128) {
            int c4 = q % (CIN / 4), pl = q / (CIN / 4);
            int p = p0 + pl;
            float4 v = make_float4(0.f, 0.f, 0.f, 0.f);
            if (p < ptot) {
                v = *(const float4*)(Yin + (size_t)p * CIN + c4 * 4);
                if (BN_IN) {
                    int c = c4 * 4;
                    v.x = fmaxf(fmaf(sA[c+0], v.x, sBc[c+0]), 0.0f);
                    v.y = fmaxf(fmaf(sA[c+1], v.y, sBc[c+1]), 0.0f);
                    v.z = fmaxf(fmaf(sA[c+2], v.z, sBc[c+2]), 0.0f);
                    v.w = fmaxf(fmaf(sA[c+3], v.w, sBc[c+3]), 0.0f);
                }
            }
            *(float4*)(Xs + pl * CIN + c4 * 4) = v;
        }
        __syncthreads();

        float acc[PT][8];
#pragma unroll
        for (int j = 0; j < PT; j++)
#pragma unroll
            for (int i = 0; i < 8; i++) acc[j][i] = 0.0f;

#pragma unroll
        for (int c = 0; c < CIN; c++) {
            float4 wa = *(const float4*)(Ws + c * COUT + tx * 4);
            float4 wb = *(const float4*)(Ws + c * COUT + HALF + tx * 4);
            float xv[PT];
#pragma unroll
            for (int j = 0; j < PT; j++) xv[j] = Xs[(ty * PT + j) * CIN + c];
#pragma unroll
            for (int j = 0; j < PT; j++) {
                acc[j][0] = fmaf(xv[j], wa.x, acc[j][0]);
                acc[j][1] = fmaf(xv[j], wa.y, acc[j][1]);
                acc[j][2] = fmaf(xv[j], wa.z, acc[j][2]);
                acc[j][3] = fmaf(xv[j], wa.w, acc[j][3]);
                acc[j][4] = fmaf(xv[j], wb.x, acc[j][4]);
                acc[j][5] = fmaf(xv[j], wb.y, acc[j][5]);
                acc[j][6] = fmaf(xv[j], wb.z, acc[j][6]);
                acc[j][7] = fmaf(xv[j], wb.w, acc[j][7]);
            }
        }

#pragma unroll
        for (int j = 0; j < PT; j++) {
            int p = p0 + ty * PT + j;
            if (p < ptot) {
                float w = g_wt[p];
                float4 o0 = make_float4(acc[j][0], acc[j][1], acc[j][2], acc[j][3]);
                float4 o1 = make_float4(acc[j][4], acc[j][5], acc[j][6], acc[j][7]);
                *(float4*)(Yout + (size_t)p * COUT + tx * 4) = o0;
                *(float4*)(Yout + (size_t)p * COUT + HALF + tx * 4) = o1;
#pragma unroll
                for (int i = 0; i < 8; i++) {
                    float v = acc[j][i];
                    float wv = w * v;
                    ps[i] += wv;
                    pq[i] += wv * v;
                }
            }
        }
        __syncthreads();
    }

    // block-level stats reduction (channel = tx*4+i or HALF+tx*4+(i-4))
#pragma unroll
    for (int i = 0; i < 8; i++) {
        int ch = (i < 4) ? (tx * 4 + i) : (HALF + tx * 4 + (i - 4));
        atomicAdd(&ssum[ch], ps[i]);
        atomicAdd(&ssq[ch],  pq[i]);
    }
    __syncthreads();
    if (tid < COUT) {
        atomicAdd(&g_sum[LOUT][tid],   (double)ssum[tid]);
        atomicAdd(&g_sumsq[LOUT][tid], (double)ssq[tid]);
    }
}

// ---------------- finalize BN affine (layer 2 only; feeds maxpool) ----------
__global__ void finalize_kernel(const float* __restrict__ gamma,
                                const float* __restrict__ beta,
                                int layer, int cout) {
    int o = threadIdx.x;
    if (o >= cout) return;
    double mean = g_sum[layer][o] / TOTAL_DIV;
    double var  = g_sumsq[layer][o] / TOTAL_DIV - mean * mean;
    double inv  = 1.0 / sqrt(var + 1e-5);
    double ga   = (double)gamma[o];
    g_A[layer][o]  = (float)(ga * inv);
    g_Bc[layer][o] = (float)((double)beta[o] - mean * ga * inv);
}

// ---------------- final BN+ReLU + max over group ----------------------------
__global__ __launch_bounds__(128)
void maxpool_kernel(float* __restrict__ feats) {
    int g = blockIdx.x;
    int o = threadIdx.x;               // 128
    int m  = g_gcnt[g];
    int st = g_gstart[g];
    float Aa = g_A[2][o], Bb = g_Bc[2][o];
    float mx = -3.4e38f;
    for (int k = 0; k < m; k++) {
        float y = g_y3[(size_t)(st + k) * 128 + o];
        float z = fmaxf(fmaf(Aa, y, Bb), 0.0f);
        mx = fmaxf(mx, z);
    }
    int b = g >> 10, s = g & (SS - 1);
    feats[((size_t)b * 128 + o) * SS + s] = mx;
}

// ---------------- launch ----------------------------------------------------
extern "C" void kernel_launch(void* const* d_in, const int* in_sizes, int n_in,
                              void* d_out, int out_size) {
    const float* xyz = (const float*)d_in[0];
    const float* pts = (const float*)d_in[1];
    const float* w0  = (const float*)d_in[2];
    const float* g0  = (const float*)d_in[4];
    const float* be0 = (const float*)d_in[5];
    const float* w1  = (const float*)d_in[6];
    const float* g1  = (const float*)d_in[8];
    const float* be1 = (const float*)d_in[9];
    const float* w2  = (const float*)d_in[10];
    const float* g2  = (const float*)d_in[12];
    const float* be2 = (const float*)d_in[13];

    float* out    = (float*)d_out;
    float* newxyz = out;                              // (B,3,S)
    float* feats  = out + (size_t)BB * 3 * SS;        // (B,128,S)

    fps_kernel<<<BB, 256>>>(xyz, newxyz);             // also zeroes accumulators
    query_gather_kernel<<<GG / 4, 128>>>(xyz, pts, newxyz);

    gemm_stats_kernel<8, 64, 0><<<1024, 128>>>(w0, g0, be0);
    gemm_stats_kernel<64, 64, 1><<<1024, 128>>>(w1, g0, be0);   // affine of layer 0
    gemm_stats_kernel<64, 128, 2><<<1024, 128>>>(w2, g1, be1);  // affine of layer 1

    finalize_kernel<<<1, 128>>>(g2, be2, 2, 128);
    maxpool_kernel<<<GG, 128>>>(feats);
}

// round 15
// speedup vs baseline: 4.2940x; 1.0702x over previous
#include <cuda_runtime.h>
#include <cuda_bf16.h>
#include <math.h>

#define BB 16
#define NN 4096
#define SS 1024
#define KK 32
#define GG (BB*SS)            // 16384 groups
#define MAXP (GG*KK)          // 524288 worst-case positions
#define TOTAL_DIV 524288.0    // BN divisor: B*K*S (= 2^19, exact fp scaling)

// ---------------- scratch (static device globals; no runtime allocation) ----
__device__ float  g_x0[(size_t)MAXP * 8];     // compacted input features (padded to 8 ch)
__device__ float  g_wt[MAXP];                  // multiplicity weight per position
__device__ int    g_gstart[GG];
__device__ int    g_gcnt[GG];
__device__ int    g_ptot;
__device__ float  g_y1[(size_t)MAXP * 64];
__device__ float  g_y2[(size_t)MAXP * 64];
__device__ float  g_y3[(size_t)MAXP * 128];
__device__ double g_sum[3][128];
__device__ double g_sumsq[3][128];
__device__ float  g_A[3][128];
__device__ float  g_Bc[3][128];

// ---------------- packed f32x2 helpers (per-lane .rn semantics == scalar) ---
__device__ __forceinline__ unsigned long long f2_pack(float lo, float hi) {
    unsigned long long r;
    asm("mov.b64 %0, {%1, %2};" : "=l"(r) : "f"(lo), "f"(hi));
    return r;
}
__device__ __forceinline__ void f2_unpack(unsigned long long v, float& lo, float& hi) {
    asm("mov.b64 {%0, %1}, %2;" : "=f"(lo), "=f"(hi) : "l"(v));
}
__device__ __forceinline__ unsigned long long f2_add(unsigned long long a, unsigned long long b) {
    unsigned long long r;
    asm("add.rn.f32x2 %0, %1, %2;" : "=l"(r) : "l"(a), "l"(b));
    return r;
}
__device__ __forceinline__ unsigned long long f2_mul(unsigned long long a, unsigned long long b) {
    unsigned long long r;
    asm("mul.rn.f32x2 %0, %1, %2;" : "=l"(r) : "l"(a), "l"(b));
    return r;
}

// ---------------- farthest point sampling (bit-exact) -----------------------
// one block per batch, 256 threads, 16 points/thread (8 f32x2 pairs).
// Block 0 additionally zeroes the global accumulators.
__global__ __launch_bounds__(256, 1)
void fps_kernel(const float* __restrict__ xyz, float* __restrict__ newxyz) {
    int b = blockIdx.x, tid = threadIdx.x;
    const float* bx = xyz + (size_t)b * 3 * NN;

    if (b == 0) {
        if (tid == 0) g_ptot = 0;
        for (int t = tid; t < 384; t += 256) {
            ((double*)g_sum)[t]   = 0.0;
            ((double*)g_sumsq)[t] = 0.0;
        }
    }

    unsigned long long px2[8], py2[8], pz2[8];
    float dist[16];
    {
        const float4* x4 = (const float4*)(bx);
        const float4* y4 = (const float4*)(bx + NN);
        const float4* z4 = (const float4*)(bx + 2 * NN);
#pragma unroll
        for (int h = 0; h < 4; h++) {
            float4 xa = x4[tid * 4 + h], ya = y4[tid * 4 + h], za = z4[tid * 4 + h];
            px2[2*h]   = f2_pack(xa.x, xa.y);
            px2[2*h+1] = f2_pack(xa.z, xa.w);
            py2[2*h]   = f2_pack(ya.x, ya.y);
            py2[2*h+1] = f2_pack(ya.z, ya.w);
            pz2[2*h]   = f2_pack(za.x, za.y);
            pz2[2*h+1] = f2_pack(za.z, za.w);
        }
    }
#pragma unroll
    for (int j = 0; j < 16; j++) dist[j] = 1e10f;

    __shared__ unsigned long long skey[2][8];   // {bits<<32 | widx} per warp
    __shared__ int fhist[SS];
    int lane = tid & 31, wid = tid >> 5;
    int farthest = 0;

    for (int it = 0; it < SS; ++it) {
        if (tid == 0) fhist[it] = farthest;
        float cx = __ldg(bx + farthest);
        float cy = __ldg(bx + NN + farthest);
        float cz = __ldg(bx + 2 * NN + farthest);
        unsigned long long ncx = f2_pack(-cx, -cx);
        unsigned long long ncy = f2_pack(-cy, -cy);
        unsigned long long ncz = f2_pack(-cz, -cz);

        // packed distance update: per lane rn(sub), rn(mul), rn((xx+yy)+zz)
#pragma unroll
        for (int k = 0; k < 8; k++) {
            unsigned long long dx = f2_add(px2[k], ncx);
            unsigned long long dy = f2_add(py2[k], ncy);
            unsigned long long dz = f2_add(pz2[k], ncz);
            unsigned long long s  = f2_add(f2_add(f2_mul(dx, dx), f2_mul(dy, dy)),
                                           f2_mul(dz, dz));
            float d0, d1;
            f2_unpack(s, d0, d1);
            dist[2*k]   = fminf(dist[2*k],   d0);
            dist[2*k+1] = fminf(dist[2*k+1], d1);
        }

        // local argmax tree over 16, first-index ties (strict > keeps lower)
        float v1[8]; int i1[8];
#pragma unroll
        for (int k = 0; k < 8; k++) {
            bool g = dist[2*k+1] > dist[2*k];
            v1[k] = g ? dist[2*k+1] : dist[2*k];
            i1[k] = g ? 2*k+1 : 2*k;
        }
        float v2[4]; int i2[4];
#pragma unroll
        for (int k = 0; k < 4; k++) {
            bool g = v1[2*k+1] > v1[2*k];
            v2[k] = g ? v1[2*k+1] : v1[2*k];
            i2[k] = g ? i1[2*k+1] : i1[2*k];
        }
        bool g0 = v2[1] > v2[0];
        float va = g0 ? v2[1] : v2[0]; int ia = g0 ? i2[1] : i2[0];
        bool g1 = v2[3] > v2[2];
        float vb = g1 ? v2[3] : v2[2]; int ib = g1 ? i2[3] : i2[2];
        bool g2 = vb > va;
        float bv = g2 ? vb : va;
        int bi = tid * 16 + (g2 ? ib : ia);

        // warp argmax via REDUX on float bits (dists >= 0 -> u32 monotone)
        unsigned bits = __float_as_uint(bv);
        unsigned wmax = __reduce_max_sync(0xffffffffu, bits);
        unsigned mm   = __ballot_sync(0xffffffffu, bits == wmax);
        int src  = __ffs(mm) - 1;                 // lowest lane = lowest index
        int widx = __shfl_sync(0xffffffffu, bi, src);

        int buf = it & 1;
        if (lane == 0)
            skey[buf][wid] = ((unsigned long long)wmax << 32) | (unsigned)widx;
        __syncthreads();

        // block argmax over 8 warp winners (lowest-wid first-index tiebreak)
        unsigned long long e = skey[buf][lane & 7];
        unsigned eb   = (unsigned)(e >> 32);
        int      ei   = (int)(unsigned)e;
        unsigned bmax = __reduce_max_sync(0xffffffffu, eb);
        unsigned wm   = __ballot_sync(0xffffffffu, eb == bmax);
        int fl = __ffs(wm) - 1;
        farthest = __shfl_sync(0xffffffffu, ei, fl);
    }

    // bulk centroid write-out
    __syncthreads();
    for (int i = tid; i < SS; i += 256) {
        int idx = fhist[i];
        newxyz[(size_t)b * 3 * SS + i]          = __ldg(bx + idx);
        newxyz[(size_t)b * 3 * SS + SS + i]     = __ldg(bx + NN + idx);
        newxyz[(size_t)b * 3 * SS + 2 * SS + i] = __ldg(bx + 2 * NN + idx);
    }
}

// ---------------- ball query + compaction + gather --------------------------
// one warp per group (b, s); FOUR points per lane via float4 loads (halves the
// LDG issue count vs the float2 version).
// Distance matches the reference's fp32 arithmetic op-for-op.
// lane l owns indices {128j+4l..128j+4l+3}; 4 ballots give the exact
// global-index-ordered prefix -> selection identical to 1-pt/lane version.
__global__ __launch_bounds__(128)
void query_gather_kernel(const float* __restrict__ xyz,
                         const float* __restrict__ pts,
                         const float* __restrict__ newxyz) {
    int gwarp = (blockIdx.x * blockDim.x + threadIdx.x) >> 5;
    int lane  = threadIdx.x & 31;
    int wslot = (threadIdx.x >> 5) & 3;
    int b = gwarp >> 10, s = gwarp & (SS - 1);

    __shared__ int sgidx[4][KK];
    int* gidx = sgidx[wslot];

    const float* bx = xyz + (size_t)b * 3 * NN;
    float cx = newxyz[(size_t)b * 3 * SS + s];
    float cy = newxyz[(size_t)b * 3 * SS + SS + s];
    float cz = newxyz[(size_t)b * 3 * SS + 2 * SS + s];
    float ns = __fadd_rn(__fadd_rn(__fmul_rn(cx, cx), __fmul_rn(cy, cy)),
                         __fmul_rn(cz, cz));

    unsigned below = (1u << lane) - 1u;
    int cnt = 0;
    for (int j = 0; j < NN / 128; j++) {
        int i0 = j * 128 + 4 * lane;
        float4 X = *(const float4*)(bx + i0);
        float4 Y = *(const float4*)(bx + NN + i0);
        float4 Z = *(const float4*)(bx + 2 * NN + i0);

        float xs[4] = {X.x, X.y, X.z, X.w};
        float ys[4] = {Y.x, Y.y, Y.z, Y.w};
        float zs[4] = {Z.x, Z.y, Z.z, Z.w};
        bool ok[4];
#pragma unroll
        for (int k = 0; k < 4; k++) {
            float nd = __fadd_rn(__fadd_rn(__fmul_rn(xs[k], xs[k]),
                                           __fmul_rn(ys[k], ys[k])),
                                 __fmul_rn(zs[k], zs[k]));
            float t  = __fmaf_rn(cz, zs[k], __fmaf_rn(cy, ys[k], __fmul_rn(cx, xs[k])));
            float d  = __fadd_rn(__fadd_rn(__fmul_rn(-2.0f, t), ns), nd);
            ok[k] = !(d > 0.04f);
        }
        unsigned m0 = __ballot_sync(0xffffffffu, ok[0]);
        unsigned m1 = __ballot_sync(0xffffffffu, ok[1]);
        unsigned m2 = __ballot_sync(0xffffffffu, ok[2]);
        unsigned m3 = __ballot_sync(0xffffffffu, ok[3]);
        int pos = cnt + __popc(m0 & below) + __popc(m1 & below)
                      + __popc(m2 & below) + __popc(m3 & below);
#pragma unroll
        for (int k = 0; k < 4; k++) {
            if (ok[k]) {
                if (pos < KK) gidx[pos] = i0 + k;
                pos++;
            }
        }
        cnt += __popc(m0) + __popc(m1) + __popc(m2) + __popc(m3);
        if (cnt >= KK) break;
    }
    int mcnt = min(cnt, KK);
    __syncwarp();

    int base = 0;
    if (lane == 0) {
        base = atomicAdd(&g_ptot, mcnt);
        g_gstart[gwarp] = base;
        g_gcnt[gwarp]   = mcnt;
    }
    base = __shfl_sync(0xffffffffu, base, 0);

    if (lane < mcnt) {
        int i = gidx[lane];
        const float* bp = pts + (size_t)b * 3 * NN;
        float* dst = g_x0 + (size_t)(base + lane) * 8;
        dst[0] = __fsub_rn(bx[i], cx);
        dst[1] = __fsub_rn(bx[NN + i], cy);
        dst[2] = __fsub_rn(bx[2 * NN + i], cz);
        dst[3] = bp[i];
        dst[4] = bp[NN + i];
        dst[5] = bp[2 * NN + i];
        dst[6] = 0.0f;
        dst[7] = 0.0f;
        g_wt[base + lane] = (lane == 0) ? (float)(KK - mcnt + 1) : 1.0f;
    }
}

// ---------------- unified GEMM + fused input-affine + output stats -----------
// grid sized so each block amortizes its fixed overhead (weight smem fill +
// per-channel double-atomic epilogue) across several tiles.
template<int CIN, int COUT, int LOUT>
__global__ __launch_bounds__(128)
void gemm_stats_kernel(const float* __restrict__ W,
                       const float* __restrict__ gamma,
                       const float* __restrict__ beta) {
    constexpr bool BN_IN = (LOUT > 0);
    constexpr int TX = COUT / 8;     // 8 or 16
    constexpr int TY = 128 / TX;     // 16 or 8
    constexpr int PT = 64 / TY;      // 4 or 8 positions per thread
    constexpr int HALF = COUT / 2;

    __shared__ float Xs[64 * CIN];       // [pos][c], contiguous in c
    __shared__ float Ws[CIN * COUT];     // [c][o]
    __shared__ float ssum[COUT], ssq[COUT];
    __shared__ float sA[64], sBc[64];

    const float* Yin  = (LOUT == 0) ? g_x0 : (LOUT == 1 ? g_y1 : g_y2);
    float*       Yout = (LOUT == 0) ? g_y1 : (LOUT == 1 ? g_y2 : g_y3);

    int tid = threadIdx.x;
    int tx = tid % TX, ty = tid / TX;

    for (int idx = tid; idx < CIN * COUT; idx += 128) {
        int c = idx % CIN, o = idx / CIN;
        float w;
        if (LOUT == 0) w = (c < 6) ? W[o * 6 + c] : 0.0f;   // W is (64, 6)
        else           w = W[o * 64 + c];                    // W is (COUT, 64)
        Ws[c * COUT + o] = w;
    }
    if (tid < COUT) { ssum[tid] = 0.0f; ssq[tid] = 0.0f; }
    if (BN_IN && tid < 64) {
        double dmean = g_sum[LOUT - 1][tid] * (1.0 / TOTAL_DIV);   // exact /2^19
        double dvar  = g_sumsq[LOUT - 1][tid] * (1.0 / TOTAL_DIV) - dmean * dmean;
        float inv = 1.0f / sqrtf((float)dvar + 1e-5f);
        float Aa  = gamma[tid] * inv;
        sA[tid]  = Aa;
        sBc[tid] = beta[tid] - (float)dmean * Aa;
    }
    __syncthreads();

    float ps[8], pq[8];
#pragma unroll
    for (int i = 0; i < 8; i++) { ps[i] = 0.0f; pq[i] = 0.0f; }

    int ptot = g_ptot;
    int ntiles = (ptot + 63) >> 6;
    for (int t = blockIdx.x; t < ntiles; t += gridDim.x) {
        int p0 = t * 64;
        // float4 tile fill: 64*CIN/4 quads
#pragma unroll 2
        for (int q = tid; q < 64 * CIN / 4; q += 128) {
            int c4 = q % (CIN / 4), pl = q / (CIN / 4);
            int p = p0 + pl;
            float4 v = make_float4(0.f, 0.f, 0.f, 0.f);
            if (p < ptot) {
                v = *(const float4*)(Yin + (size_t)p * CIN + c4 * 4);
                if (BN_IN) {
                    int c = c4 * 4;
                    v.x = fmaxf(fmaf(sA[c+0], v.x, sBc[c+0]), 0.0f);
                    v.y = fmaxf(fmaf(sA[c+1], v.y, sBc[c+1]), 0.0f);
                    v.z = fmaxf(fmaf(sA[c+2], v.z, sBc[c+2]), 0.0f);
                    v.w = fmaxf(fmaf(sA[c+3], v.w, sBc[c+3]), 0.0f);
                }
            }
            *(float4*)(Xs + pl * CIN + c4 * 4) = v;
        }
        __syncthreads();

        float acc[PT][8];
#pragma unroll
        for (int j = 0; j < PT; j++)
#pragma unroll
            for (int i = 0; i < 8; i++) acc[j][i] = 0.0f;

#pragma unroll
        for (int c = 0; c < CIN; c++) {
            float4 wa = *(const float4*)(Ws + c * COUT + tx * 4);
            float4 wb = *(const float4*)(Ws + c * COUT + HALF + tx * 4);
            float xv[PT];
#pragma unroll
            for (int j = 0; j < PT; j++) xv[j] = Xs[(ty * PT + j) * CIN + c];
#pragma unroll
            for (int j = 0; j < PT; j++) {
                acc[j][0] = fmaf(xv[j], wa.x, acc[j][0]);
                acc[j][1] = fmaf(xv[j], wa.y, acc[j][1]);
                acc[j][2] = fmaf(xv[j], wa.z, acc[j][2]);
                acc[j][3] = fmaf(xv[j], wa.w, acc[j][3]);
                acc[j][4] = fmaf(xv[j], wb.x, acc[j][4]);
                acc[j][5] = fmaf(xv[j], wb.y, acc[j][5]);
                acc[j][6] = fmaf(xv[j], wb.z, acc[j][6]);
                acc[j][7] = fmaf(xv[j], wb.w, acc[j][7]);
            }
        }

#pragma unroll
        for (int j = 0; j < PT; j++) {
            int p = p0 + ty * PT + j;
            if (p < ptot) {
                float w = g_wt[p];
                float4 o0 = make_float4(acc[j][0], acc[j][1], acc[j][2], acc[j][3]);
                float4 o1 = make_float4(acc[j][4], acc[j][5], acc[j][6], acc[j][7]);
                *(float4*)(Yout + (size_t)p * COUT + tx * 4) = o0;
                *(float4*)(Yout + (size_t)p * COUT + HALF + tx * 4) = o1;
#pragma unroll
                for (int i = 0; i < 8; i++) {
                    float v = acc[j][i];
                    float wv = w * v;
                    ps[i] += wv;
                    pq[i] += wv * v;
                }
            }
        }
        __syncthreads();
    }

    // block-level stats reduction (channel = tx*4+i or HALF+tx*4+(i-4))
#pragma unroll
    for (int i = 0; i < 8; i++) {
        int ch = (i < 4) ? (tx * 4 + i) : (HALF + tx * 4 + (i - 4));
        atomicAdd(&ssum[ch], ps[i]);
        atomicAdd(&ssq[ch],  pq[i]);
    }
    __syncthreads();
    if (tid < COUT) {
        atomicAdd(&g_sum[LOUT][tid],   (double)ssum[tid]);
        atomicAdd(&g_sumsq[LOUT][tid], (double)ssq[tid]);
    }
}

// ---------------- finalize BN affine (layer 2 only; feeds maxpool) ----------
__global__ void finalize_kernel(const float* __restrict__ gamma,
                                const float* __restrict__ beta,
                                int layer, int cout) {
    int o = threadIdx.x;
    if (o >= cout) return;
    double mean = g_sum[layer][o] / TOTAL_DIV;
    double var  = g_sumsq[layer][o] / TOTAL_DIV - mean * mean;
    double inv  = 1.0 / sqrt(var + 1e-5);
    double ga   = (double)gamma[o];
    g_A[layer][o]  = (float)(ga * inv);
    g_Bc[layer][o] = (float)((double)beta[o] - mean * ga * inv);
}

// ---------------- final BN+ReLU + max over group ----------------------------
__global__ __launch_bounds__(128)
void maxpool_kernel(float* __restrict__ feats) {
    int g = blockIdx.x;
    int o = threadIdx.x;               // 128
    int m  = g_gcnt[g];
    int st = g_gstart[g];
    float Aa = g_A[2][o], Bb = g_Bc[2][o];
    float mx = -3.4e38f;
    for (int k = 0; k < m; k++) {
        float y = g_y3[(size_t)(st + k) * 128 + o];
        float z = fmaxf(fmaf(Aa, y, Bb), 0.0f);
        mx = fmaxf(mx, z);
    }
    int b = g >> 10, s = g & (SS - 1);
    feats[((size_t)b * 128 + o) * SS + s] = mx;
}

// ---------------- launch ----------------------------------------------------
extern "C" void kernel_launch(void* const* d_in, const int* in_sizes, int n_in,
                              void* d_out, int out_size) {
    const float* xyz = (const float*)d_in[0];
    const float* pts = (const float*)d_in[1];
    const float* w0  = (const float*)d_in[2];
    const float* g0  = (const float*)d_in[4];
    const float* be0 = (const float*)d_in[5];
    const float* w1  = (const float*)d_in[6];
    const float* g1  = (const float*)d_in[8];
    const float* be1 = (const float*)d_in[9];
    const float* w2  = (const float*)d_in[10];
    const float* g2  = (const float*)d_in[12];
    const float* be2 = (const float*)d_in[13];

    float* out    = (float*)d_out;
    float* newxyz = out;                              // (B,3,S)
    float* feats  = out + (size_t)BB * 3 * SS;        // (B,128,S)

    fps_kernel<<<BB, 256>>>(xyz, newxyz);             // also zeroes accumulators
    query_gather_kernel<<<GG / 4, 128>>>(xyz, pts, newxyz);

    gemm_stats_kernel<8, 64, 0><<<256, 128>>>(w0, g0, be0);
    gemm_stats_kernel<64, 64, 1><<<256, 128>>>(w1, g0, be0);   // affine of layer 0
    gemm_stats_kernel<64, 128, 2><<<256, 128>>>(w2, g1, be1);  // affine of layer 1

    finalize_kernel<<<1, 128>>>(g2, be2, 2, 128);
    maxpool_kernel<<<GG, 128>>>(feats);
}